// round 2
// baseline (speedup 1.0000x reference)
#include <cuda_runtime.h>

#define NNODES 100000
#define NFEAT  128
#define HID    128   // 8 heads * 16
#define H1     8
#define NCLS   40
#define NEG    0.2f

// ---------------- scratch (device globals; no runtime alloc) ----------------
__device__ __align__(16) float g_h1  [NNODES * HID];
__device__ __align__(16) float g_res1[NNODES * HID];
__device__ __align__(16) float g_as1 [NNODES * H1];
__device__ __align__(16) float g_ad1 [NNODES * H1];
__device__ __align__(16) float g_num1[NNODES * HID];
__device__ __align__(16) float g_den1[NNODES * H1];
__device__ __align__(16) float g_h   [NNODES * HID];
__device__ __align__(16) float g_h2  [NNODES * NCLS];
__device__ __align__(16) float g_res2[NNODES * NCLS];
__device__ __align__(16) float g_as2 [NNODES];
__device__ __align__(16) float g_ad2 [NNODES];
__device__ __align__(16) float g_num2[NNODES * NCLS];
__device__ __align__(16) float g_den2[NNODES];
__device__ int g_is64;

// ---------------- edge_index dtype detection ---------------------------------
// If the buffer holds int64 node ids (< 2^31), every odd 32-bit word is the
// zero high-half. If it holds int32 ids, odd words are random ids (sum != 0
// with overwhelming probability). Deterministic on fixed input.
__global__ void k_detect(const int* __restrict__ ei32)
{
    if (threadIdx.x == 0 && blockIdx.x == 0) {
        long long s = 0;
        for (int i = 1; i < 128; i += 2) s += ei32[i];
        g_is64 = (s == 0) ? 1 : 0;
    }
}

__device__ __forceinline__ void load_edge(const int* __restrict__ ei, int E,
                                          int gw, int& s, int& d)
{
    if (gw < E) {
        if (g_is64) {
            const long long* e64 = (const long long*)ei;
            s = (int)e64[gw];
            d = (int)e64[E + gw];
        } else {
            s = ei[gw];
            d = ei[E + gw];
        }
    } else {
        s = d = gw - E;   // self loop
    }
}

// ---------------- Layer 1 node GEMM: h1 = x@W1, res1 = x@res1_W + b ----------
__global__ void k_gemm1(const float* __restrict__ x,
                        const float* __restrict__ W1,
                        const float* __restrict__ resW,
                        const float* __restrict__ res_b,
                        const float* __restrict__ att_src,
                        const float* __restrict__ att_dst)
{
    __shared__ float xs[16 * 128];
    const int row0 = blockIdx.x * 16;
    const int j = threadIdx.x;

    for (int i = j; i < 16 * 128; i += 256)
        xs[i] = x[(row0 + (i >> 7)) * NFEAT + (i & 127)];
    __syncthreads();

    float acc[16];
#pragma unroll
    for (int r = 0; r < 16; r++) acc[r] = 0.f;

    const float* Wc = (j < 128) ? (W1 + j) : (resW + (j - 128));
#pragma unroll 4
    for (int k = 0; k < 128; k++) {
        float w = Wc[k * 128];
#pragma unroll
        for (int r = 0; r < 16; r++) acc[r] += xs[r * 128 + k] * w;
    }

    if (j < 128) {
        const float as = att_src[j];   // (8,16) row-major: head=j>>4, c=j&15
        const float ad = att_dst[j];
#pragma unroll
        for (int r = 0; r < 16; r++) {
            const int gr = row0 + r;
            const float v = acc[r];
            g_h1 [gr * HID + j] = v;
            g_num1[gr * HID + j] = 0.f;
            float vs = v * as, vd = v * ad;
#pragma unroll
            for (int o = 8; o; o >>= 1) {        // reduce 16-lane head groups
                vs += __shfl_xor_sync(0xffffffffu, vs, o);
                vd += __shfl_xor_sync(0xffffffffu, vd, o);
            }
            if ((j & 15) == 0) {
                g_as1[gr * H1 + (j >> 4)] = vs;
                g_ad1[gr * H1 + (j >> 4)] = vd;
            }
            if (j < 8) g_den1[gr * H1 + j] = 0.f;
        }
    } else {
        const int jj = j - 128;
        const float b = res_b[jj];
#pragma unroll
        for (int r = 0; r < 16; r++)
            g_res1[(row0 + r) * HID + jj] = acc[r] + b;
    }
}

// ---------------- Layer 1 edge pass (single fused pass, no segment-max) -----
__global__ void k_edge1(const int* __restrict__ ei, int E)
{
    const int gw   = (blockIdx.x * blockDim.x + threadIdx.x) >> 5;
    const int lane = threadIdx.x & 31;
    if (gw >= E + NNODES) return;

    int s, d;
    load_edge(ei, E, gw, s, d);

    const int h = lane & 7;
    float l = g_as1[s * H1 + h] + g_ad1[d * H1 + h];
    l = (l > 0.f) ? l : NEG * l;
    const float ew = __expf(l);

    if (lane < 8) atomicAdd(&g_den1[d * H1 + lane], ew);

    const float w = __shfl_sync(0xffffffffu, ew, lane >> 2); // head of this float4

    float4 v = ((const float4*)(g_h1 + (size_t)s * HID))[lane];
    float4 m; m.x = v.x * w; m.y = v.y * w; m.z = v.z * w; m.w = v.w * w;
    atomicAdd(((float4*)(g_num1 + (size_t)d * HID)) + lane, m);
}

// ---------------- Layer 1 finalize: h = elu(num/den + bias1) + res1 ---------
__global__ void k_fin1(const float* __restrict__ bias1)
{
    const int idx = blockIdx.x * blockDim.x + threadIdx.x;
    if (idx >= NNODES * HID) return;
    const int n = idx >> 7, j = idx & 127;
    const float den = g_den1[n * H1 + (j >> 4)];
    float v = g_num1[idx] / den + bias1[j];
    v = (v > 0.f) ? v : expm1f(v);           // ELU alpha=1
    g_h[idx] = v + g_res1[idx];
}

// ---------------- Layer 2 node GEMM ------------------------------------------
__global__ void k_gemm2(const float* __restrict__ W2,
                        const float* __restrict__ res2W,
                        const float* __restrict__ res2_b,
                        const float* __restrict__ att_src2,
                        const float* __restrict__ att_dst2)
{
    __shared__ float xs[16 * 128];
    __shared__ float sred[2 * 16 * NCLS];
    const int row0 = blockIdx.x * 16;
    const int j = threadIdx.x;

    for (int i = j; i < 16 * 128; i += 96)
        xs[i] = g_h[(row0 + (i >> 7)) * HID + (i & 127)];
    __syncthreads();

    float acc[16];
#pragma unroll
    for (int r = 0; r < 16; r++) acc[r] = 0.f;

    if (j < 80) {
        const float* Wc = (j < NCLS) ? (W2 + j) : (res2W + (j - NCLS));
#pragma unroll 4
        for (int k = 0; k < 128; k++) {
            float w = Wc[k * NCLS];
#pragma unroll
            for (int r = 0; r < 16; r++) acc[r] += xs[r * 128 + k] * w;
        }
    }

    if (j < NCLS) {
        const float as = att_src2[j];
        const float ad = att_dst2[j];
#pragma unroll
        for (int r = 0; r < 16; r++) {
            const int gr = row0 + r;
            g_h2 [gr * NCLS + j] = acc[r];
            g_num2[gr * NCLS + j] = 0.f;
            sred[r * NCLS + j]             = acc[r] * as;
            sred[16 * NCLS + r * NCLS + j] = acc[r] * ad;
        }
    } else if (j < 80) {
        const int jj = j - NCLS;
        const float b = res2_b[jj];
#pragma unroll
        for (int r = 0; r < 16; r++)
            g_res2[(row0 + r) * NCLS + jj] = acc[r] + b;
    }
    __syncthreads();

    if (j < 16) {
        float ss = 0.f, dd = 0.f;
        for (int c = 0; c < NCLS; c++) {
            ss += sred[j * NCLS + c];
            dd += sred[16 * NCLS + j * NCLS + c];
        }
        g_as2[row0 + j] = ss;
        g_ad2[row0 + j] = dd;
        g_den2[row0 + j] = 0.f;
    }
}

// ---------------- Layer 2 edge pass ------------------------------------------
__global__ void k_edge2(const int* __restrict__ ei, int E)
{
    const int gw   = (blockIdx.x * blockDim.x + threadIdx.x) >> 5;
    const int lane = threadIdx.x & 31;
    if (gw >= E + NNODES) return;

    int s, d;
    load_edge(ei, E, gw, s, d);

    float l = g_as2[s] + g_ad2[d];
    l = (l > 0.f) ? l : NEG * l;
    const float w = __expf(l);

    if (lane == 0) atomicAdd(&g_den2[d], w);
    if (lane < 10) {  // 40 floats = 10 float4; 160B rows keep 16B alignment
        float4 v = ((const float4*)(g_h2 + (size_t)s * NCLS))[lane];
        float4 m; m.x = v.x * w; m.y = v.y * w; m.z = v.z * w; m.w = v.w * w;
        atomicAdd(((float4*)(g_num2 + (size_t)d * NCLS)) + lane, m);
    }
}

// ---------------- Layer 2 finalize + log_softmax -> d_out --------------------
__global__ void k_fin2(const float* __restrict__ bias2, float* __restrict__ out)
{
    const int gw   = (blockIdx.x * blockDim.x + threadIdx.x) >> 5;
    const int lane = threadIdx.x & 31;
    if (gw >= NNODES) return;

    const float inv = 1.f / g_den2[gw];
    const int base = gw * NCLS;

    float v0 = g_num2[base + lane] * inv + bias2[lane] + g_res2[base + lane];
    float v1 = -1e30f;
    if (lane < 8)
        v1 = g_num2[base + 32 + lane] * inv + bias2[32 + lane] + g_res2[base + 32 + lane];

    float m = fmaxf(v0, v1);
#pragma unroll
    for (int o = 16; o; o >>= 1) m = fmaxf(m, __shfl_xor_sync(0xffffffffu, m, o));
    float se = __expf(v0 - m) + ((lane < 8) ? __expf(v1 - m) : 0.f);
#pragma unroll
    for (int o = 16; o; o >>= 1) se += __shfl_xor_sync(0xffffffffu, se, o);
    const float lse = m + logf(se);

    out[base + lane] = v0 - lse;
    if (lane < 8) out[base + 32 + lane] = v1 - lse;
}

// ---------------- launch ------------------------------------------------------
extern "C" void kernel_launch(void* const* d_in, const int* in_sizes, int n_in,
                              void* d_out, int out_size)
{
    const float* x   = (const float*)d_in[0];
    const int*   ei  = (const int*)d_in[1];
    const float* W1  = (const float*)d_in[2];
    const float* as1 = (const float*)d_in[3];
    const float* ad1 = (const float*)d_in[4];
    const float* b1  = (const float*)d_in[5];
    const float* W2  = (const float*)d_in[6];
    const float* as2 = (const float*)d_in[7];
    const float* ad2 = (const float*)d_in[8];
    const float* b2  = (const float*)d_in[9];
    const float* r1W = (const float*)d_in[10];
    const float* r1b = (const float*)d_in[11];
    const float* r2W = (const float*)d_in[12];
    const float* r2b = (const float*)d_in[13];

    const int E  = in_sizes[1] / 2;
    const int EE = E + NNODES;
    const int edge_blocks = (EE + 7) / 8;   // 8 edge-warps per 256-thread block

    k_detect<<<1, 32>>>(ei);
    k_gemm1<<<NNODES / 16, 256>>>(x, W1, r1W, r1b, as1, ad1);
    k_edge1<<<edge_blocks, 256>>>(ei, E);
    k_fin1 <<<(NNODES * HID) / 256, 256>>>(b1);
    k_gemm2<<<NNODES / 16, 96>>>(W2, r2W, r2b, as2, ad2);
    k_edge2<<<edge_blocks, 256>>>(ei, E);
    k_fin2 <<<(NNODES + 7) / 8, 256>>>(b2, (float*)d_out);
}

// round 3
// speedup vs baseline: 1.1246x; 1.1246x over previous
#include <cuda_runtime.h>

#define NNODES 100000
#define NFEAT  128
#define HID    128   // 8 heads * 16
#define H1     8
#define NCLS   40
#define NEG    0.2f

typedef unsigned long long ull;

// ---------------- scratch (device globals; no runtime alloc) ----------------
__device__ __align__(16) float g_h1  [NNODES * HID];
__device__ __align__(16) float g_res1[NNODES * HID];
__device__ __align__(16) float g_as1 [NNODES * H1];
__device__ __align__(16) float g_ad1 [NNODES * H1];
__device__ __align__(16) float g_num1[NNODES * HID];
__device__ __align__(16) float g_den1[NNODES * H1];
__device__ __align__(16) float g_h2  [NNODES * NCLS];
__device__ __align__(16) float g_res2[NNODES * NCLS];
__device__ __align__(16) float g_as2 [NNODES];
__device__ __align__(16) float g_ad2 [NNODES];
__device__ __align__(16) float g_num2[NNODES * NCLS];
__device__ __align__(16) float g_den2[NNODES];
__device__ int g_is64;

// ---------------- f32x2 helpers ----------------------------------------------
__device__ __forceinline__ ull pack2(float v) {
    ull r; asm("mov.b64 %0, {%1,%1};" : "=l"(r) : "f"(v)); return r;
}
__device__ __forceinline__ void unpack2(ull v, float& lo, float& hi) {
    asm("mov.b64 {%0,%1}, %2;" : "=f"(lo), "=f"(hi) : "l"(v));
}
__device__ __forceinline__ void fma2(ull& acc, ull a, ull b) {
    asm("fma.rn.f32x2 %0, %1, %2, %0;" : "+l"(acc) : "l"(a), "l"(b));
}
__device__ __forceinline__ ull mul2(ull a, ull b) {
    ull c; asm("mul.rn.f32x2 %0, %1, %2;" : "=l"(c) : "l"(a), "l"(b)); return c;
}
__device__ __forceinline__ ull add2(ull a, ull b) {
    ull c; asm("add.rn.f32x2 %0, %1, %2;" : "=l"(c) : "l"(a), "l"(b)); return c;
}
__device__ __forceinline__ ull shfl_xor64(ull v, int o) {
    double d = __longlong_as_double((long long)v);
    d = __shfl_xor_sync(0xffffffffu, d, o);
    return (ull)__double_as_longlong(d);
}

// ---------------- edge_index dtype detection ---------------------------------
__global__ void k_detect(const int* __restrict__ ei32)
{
    if (threadIdx.x == 0 && blockIdx.x == 0) {
        long long s = 0;
        for (int i = 1; i < 128; i += 2) s += ei32[i];
        g_is64 = (s == 0) ? 1 : 0;
    }
}

__device__ __forceinline__ void load_edge(const int* __restrict__ ei, int E,
                                          int gw, int& s, int& d)
{
    if (gw < E) {
        if (g_is64) {
            const long long* e64 = (const long long*)ei;
            s = (int)e64[gw];
            d = (int)e64[E + gw];
        } else {
            s = ei[gw];
            d = ei[E + gw];
        }
    } else {
        s = d = gw - E;   // self loop
    }
}

// ---------------- Layer 1 node GEMM (f32x2): 32 rows x 256 cols per block ----
// 128 threads; thread t owns W1 col t AND res1_W col t.
__global__ void __launch_bounds__(128) k_gemm1(
        const float* __restrict__ x,
        const float* __restrict__ W1,
        const float* __restrict__ resW,
        const float* __restrict__ res_b,
        const float* __restrict__ att_src,
        const float* __restrict__ att_dst)
{
    __shared__ float xs[128 * 34];           // [k][34] (rows 0..31, pad 2)
    const int row0 = blockIdx.x * 32;
    const int t = threadIdx.x;

    // load & transpose x tile: thread t loads column k=t, all 32 rows
#pragma unroll 4
    for (int r = 0; r < 32; r++)
        xs[t * 34 + r] = x[(row0 + r) * NFEAT + t];
    __syncthreads();

    ull accA[16], accB[16];
#pragma unroll
    for (int i = 0; i < 16; i++) { accA[i] = 0ull; accB[i] = 0ull; }

    const float* WA = W1 + t;     // stride 128
    const float* WB = resW + t;   // stride 128

#pragma unroll 2
    for (int k = 0; k < 128; k++) {
        const ull wa = pack2(WA[k * 128]);
        const ull wb = pack2(WB[k * 128]);
        const ull* xp = (const ull*)(xs + k * 34);
#pragma unroll
        for (int i = 0; i < 16; i++) {
            const ull xv = xp[i];
            fma2(accA[i], xv, wa);
            fma2(accB[i], xv, wb);
        }
    }

    // epilogue
    const ull asp = pack2(att_src[t]);   // (8,16) row-major: head=t>>4
    const ull adp = pack2(att_dst[t]);
    const ull bbp = pack2(res_b[t]);
    const int head = t >> 4;

#pragma unroll
    for (int i = 0; i < 16; i++) {
        const int gr = row0 + 2 * i;
        float lo, hi;
        unpack2(accA[i], lo, hi);
        g_h1[gr * HID + t]       = lo;
        g_h1[(gr + 1) * HID + t] = hi;
        g_num1[gr * HID + t]       = 0.f;
        g_num1[(gr + 1) * HID + t] = 0.f;

        // attention scalars: reduce over the 16 cols of this head
        ull vs = mul2(accA[i], asp);
        ull vd = mul2(accA[i], adp);
#pragma unroll
        for (int o = 8; o; o >>= 1) {
            vs = add2(vs, shfl_xor64(vs, o));
            vd = add2(vd, shfl_xor64(vd, o));
        }
        if ((t & 15) == 0) {
            float s0, s1, d0, d1;
            unpack2(vs, s0, s1); unpack2(vd, d0, d1);
            g_as1[gr * H1 + head]       = s0;
            g_as1[(gr + 1) * H1 + head] = s1;
            g_ad1[gr * H1 + head]       = d0;
            g_ad1[(gr + 1) * H1 + head] = d1;
        }

        ull rb = add2(accB[i], bbp);
        unpack2(rb, lo, hi);
        g_res1[gr * HID + t]       = lo;
        g_res1[(gr + 1) * HID + t] = hi;
    }

    if (t < 8) {
#pragma unroll 4
        for (int r = 0; r < 32; r++)
            g_den1[(row0 + r) * H1 + t] = 0.f;
    }
}

// ---------------- Layer 1 edge pass (single fused pass, no segment-max) -----
__global__ void k_edge1(const int* __restrict__ ei, int E)
{
    const int gw   = (blockIdx.x * blockDim.x + threadIdx.x) >> 5;
    const int lane = threadIdx.x & 31;
    if (gw >= E + NNODES) return;

    int s, d;
    load_edge(ei, E, gw, s, d);

    const int h = lane & 7;
    float l = g_as1[s * H1 + h] + g_ad1[d * H1 + h];
    l = (l > 0.f) ? l : NEG * l;
    const float ew = __expf(l);

    if (lane < 8) atomicAdd(&g_den1[d * H1 + lane], ew);

    const float w = __shfl_sync(0xffffffffu, ew, lane >> 2); // head of this float4

    float4 v = ((const float4*)(g_h1 + (size_t)s * HID))[lane];
    float4 m; m.x = v.x * w; m.y = v.y * w; m.z = v.z * w; m.w = v.w * w;
    atomicAdd(((float4*)(g_num1 + (size_t)d * HID)) + lane, m);
}

// ---------------- Layer 2 node GEMM (f32x2), fused with layer-1 finalize -----
// 96 threads, 32 rows per block. Threads t<40 -> W2 col t; t in [40,80) ->
// res2_W col t-40. All threads cooperatively build h = elu(num/den+b1)+res1.
__global__ void __launch_bounds__(96) k_gemm2(
        const float* __restrict__ W2,
        const float* __restrict__ res2W,
        const float* __restrict__ res2_b,
        const float* __restrict__ att_src2,
        const float* __restrict__ att_dst2,
        const float* __restrict__ bias1)
{
    __shared__ float xs[128 * 34];           // [c][34]
    __shared__ float sred[2 * 32 * NCLS];    // per-row att partials
    const int row0 = blockIdx.x * 32;
    const int t = threadIdx.x;

    // fused layer-1 finalize: h[n][c] = elu(num1/den1 + b1) + res1
    for (int idx = t; idx < 32 * 128; idx += 96) {
        const int r = idx >> 7, c = idx & 127;
        const int n = row0 + r;
        const float den = g_den1[n * H1 + (c >> 4)];
        float v = __fdividef(g_num1[n * HID + c], den) + bias1[c];
        v = (v > 0.f) ? v : (__expf(v) - 1.f);
        xs[c * 34 + r] = v + g_res1[n * HID + c];
    }
    __syncthreads();

    ull acc[16];
#pragma unroll
    for (int i = 0; i < 16; i++) acc[i] = 0ull;

    if (t < 80) {
        const float* Wc = (t < NCLS) ? (W2 + t) : (res2W + (t - NCLS));
#pragma unroll 2
        for (int k = 0; k < 128; k++) {
            const ull w = pack2(Wc[k * NCLS]);
            const ull* xp = (const ull*)(xs + k * 34);
#pragma unroll
            for (int i = 0; i < 16; i++)
                fma2(acc[i], xp[i], w);
        }
    }

    if (t < NCLS) {
        const float as = att_src2[t];
        const float ad = att_dst2[t];
#pragma unroll
        for (int i = 0; i < 16; i++) {
            const int gr = row0 + 2 * i;
            float lo, hi;
            unpack2(acc[i], lo, hi);
            g_h2[gr * NCLS + t]       = lo;
            g_h2[(gr + 1) * NCLS + t] = hi;
            g_num2[gr * NCLS + t]       = 0.f;
            g_num2[(gr + 1) * NCLS + t] = 0.f;
            sred[(2 * i) * NCLS + t]     = lo * as;
            sred[(2 * i + 1) * NCLS + t] = hi * as;
            sred[32 * NCLS + (2 * i) * NCLS + t]     = lo * ad;
            sred[32 * NCLS + (2 * i + 1) * NCLS + t] = hi * ad;
        }
    } else if (t < 80) {
        const float b = res2_b[t - NCLS];
        const ull bp = pack2(b);
#pragma unroll
        for (int i = 0; i < 16; i++) {
            const int gr = row0 + 2 * i;
            float lo, hi;
            unpack2(add2(acc[i], bp), lo, hi);
            g_res2[gr * NCLS + (t - NCLS)]       = lo;
            g_res2[(gr + 1) * NCLS + (t - NCLS)] = hi;
        }
    }
    __syncthreads();

    if (t < 32) {
        float ss = 0.f, dd = 0.f;
#pragma unroll 8
        for (int c = 0; c < NCLS; c++) {
            ss += sred[t * NCLS + c];
            dd += sred[32 * NCLS + t * NCLS + c];
        }
        g_as2[row0 + t] = ss;
        g_ad2[row0 + t] = dd;
        g_den2[row0 + t] = 0.f;
    }
}

// ---------------- Layer 2 edge pass ------------------------------------------
__global__ void k_edge2(const int* __restrict__ ei, int E)
{
    const int gw   = (blockIdx.x * blockDim.x + threadIdx.x) >> 5;
    const int lane = threadIdx.x & 31;
    if (gw >= E + NNODES) return;

    int s, d;
    load_edge(ei, E, gw, s, d);

    float l = g_as2[s] + g_ad2[d];
    l = (l > 0.f) ? l : NEG * l;
    const float w = __expf(l);

    if (lane == 0) atomicAdd(&g_den2[d], w);
    if (lane < 10) {  // 40 floats = 10 float4; 160B rows keep 16B alignment
        float4 v = ((const float4*)(g_h2 + (size_t)s * NCLS))[lane];
        float4 m; m.x = v.x * w; m.y = v.y * w; m.z = v.z * w; m.w = v.w * w;
        atomicAdd(((float4*)(g_num2 + (size_t)d * NCLS)) + lane, m);
    }
}

// ---------------- Layer 2 finalize + log_softmax -> d_out --------------------
__global__ void k_fin2(const float* __restrict__ bias2, float* __restrict__ out)
{
    const int gw   = (blockIdx.x * blockDim.x + threadIdx.x) >> 5;
    const int lane = threadIdx.x & 31;
    if (gw >= NNODES) return;

    const float inv = 1.f / g_den2[gw];
    const int base = gw * NCLS;

    float v0 = g_num2[base + lane] * inv + bias2[lane] + g_res2[base + lane];
    float v1 = -1e30f;
    if (lane < 8)
        v1 = g_num2[base + 32 + lane] * inv + bias2[32 + lane] + g_res2[base + 32 + lane];

    float m = fmaxf(v0, v1);
#pragma unroll
    for (int o = 16; o; o >>= 1) m = fmaxf(m, __shfl_xor_sync(0xffffffffu, m, o));
    float se = __expf(v0 - m) + ((lane < 8) ? __expf(v1 - m) : 0.f);
#pragma unroll
    for (int o = 16; o; o >>= 1) se += __shfl_xor_sync(0xffffffffu, se, o);
    const float lse = m + logf(se);

    out[base + lane] = v0 - lse;
    if (lane < 8) out[base + 32 + lane] = v1 - lse;
}

// ---------------- launch ------------------------------------------------------
extern "C" void kernel_launch(void* const* d_in, const int* in_sizes, int n_in,
                              void* d_out, int out_size)
{
    const float* x   = (const float*)d_in[0];
    const int*   ei  = (const int*)d_in[1];
    const float* W1  = (const float*)d_in[2];
    const float* as1 = (const float*)d_in[3];
    const float* ad1 = (const float*)d_in[4];
    const float* b1  = (const float*)d_in[5];
    const float* W2  = (const float*)d_in[6];
    const float* as2 = (const float*)d_in[7];
    const float* ad2 = (const float*)d_in[8];
    const float* b2  = (const float*)d_in[9];
    const float* r1W = (const float*)d_in[10];
    const float* r1b = (const float*)d_in[11];
    const float* r2W = (const float*)d_in[12];
    const float* r2b = (const float*)d_in[13];

    const int E  = in_sizes[1] / 2;
    const int EE = E + NNODES;
    const int edge_blocks = (EE + 7) / 8;   // 8 edge-warps per 256-thread block

    k_detect<<<1, 32>>>(ei);
    k_gemm1<<<NNODES / 32, 128>>>(x, W1, r1W, r1b, as1, ad1);
    k_edge1<<<edge_blocks, 256>>>(ei, E);
    k_gemm2<<<NNODES / 32, 96>>>(W2, r2W, r2b, as2, ad2, b1);
    k_edge2<<<edge_blocks, 256>>>(ei, E);
    k_fin2 <<<(NNODES + 7) / 8, 256>>>(b2, (float*)d_out);
}

// round 4
// speedup vs baseline: 1.3037x; 1.1592x over previous
#include <cuda_runtime.h>

#define NNODES 100000
#define NFEAT  128
#define HID    128   // 8 heads * 16
#define H1     8
#define NCLS   40
#define NEG    0.2f

typedef unsigned long long ull;

// ---------------- scratch (device globals; no runtime alloc) ----------------
__device__ __align__(16) float g_h1  [NNODES * HID];
__device__ __align__(16) float g_res1[NNODES * HID];
__device__ __align__(16) float g_as1 [NNODES * H1];
__device__ __align__(16) float g_ad1 [NNODES * H1];
__device__ __align__(16) float g_num1[NNODES * HID];
__device__ __align__(16) float g_den1[NNODES * H1];
__device__ __align__(16) float g_h2  [NNODES * NCLS];
__device__ __align__(16) float g_res2[NNODES * NCLS];
__device__ __align__(16) float g_as2 [NNODES];
__device__ __align__(16) float g_ad2 [NNODES];
__device__ __align__(16) float g_num2[NNODES * NCLS];
__device__ __align__(16) float g_den2[NNODES];
__device__ int g_is64;

// ---------------- f32x2 helpers ----------------------------------------------
__device__ __forceinline__ ull pack2(float v) {
    ull r; asm("mov.b64 %0, {%1,%1};" : "=l"(r) : "f"(v)); return r;
}
__device__ __forceinline__ void unpack2(ull v, float& lo, float& hi) {
    asm("mov.b64 {%0,%1}, %2;" : "=f"(lo), "=f"(hi) : "l"(v));
}
__device__ __forceinline__ void fma2(ull& acc, ull a, ull b) {
    asm("fma.rn.f32x2 %0, %1, %2, %0;" : "+l"(acc) : "l"(a), "l"(b));
}
__device__ __forceinline__ ull mul2(ull a, ull b) {
    ull c; asm("mul.rn.f32x2 %0, %1, %2;" : "=l"(c) : "l"(a), "l"(b)); return c;
}
__device__ __forceinline__ ull add2(ull a, ull b) {
    ull c; asm("add.rn.f32x2 %0, %1, %2;" : "=l"(c) : "l"(a), "l"(b)); return c;
}
__device__ __forceinline__ ull shfl_xor64(ull v, int o) {
    double d = __longlong_as_double((long long)v);
    d = __shfl_xor_sync(0xffffffffu, d, o);
    return (ull)__double_as_longlong(d);
}

// ---------------- edge_index dtype detection ---------------------------------
__global__ void k_detect(const int* __restrict__ ei32)
{
    if (threadIdx.x == 0 && blockIdx.x == 0) {
        long long s = 0;
        for (int i = 1; i < 128; i += 2) s += ei32[i];
        g_is64 = (s == 0) ? 1 : 0;
    }
}

__device__ __forceinline__ void load_edge(const int* __restrict__ ei, int E,
                                          int gw, int& s, int& d)
{
    if (gw < E) {
        if (g_is64) {
            const long long* e64 = (const long long*)ei;
            s = (int)e64[gw];
            d = (int)e64[E + gw];
        } else {
            s = ei[gw];
            d = ei[E + gw];
        }
    } else {
        s = d = gw - E;   // self loop
    }
}

// ---------------- Layer 1 node GEMM (f32x2): 32 rows x 256 cols per block ----
// 128 threads; thread t owns W1 col t AND res1_W col t. LDS.128 x reads.
__global__ void __launch_bounds__(128) k_gemm1(
        const float* __restrict__ x,
        const float* __restrict__ W1,
        const float* __restrict__ resW,
        const float* __restrict__ res_b,
        const float* __restrict__ att_src,
        const float* __restrict__ att_dst)
{
    __shared__ __align__(16) float xs[128 * 36];  // [k][36] (rows 0..31, pad 4)
    const int row0 = blockIdx.x * 32;
    const int t = threadIdx.x;

    // load & transpose x tile: thread t loads column k=t, all 32 rows
#pragma unroll 4
    for (int r = 0; r < 32; r++)
        xs[t * 36 + r] = x[(row0 + r) * NFEAT + t];
    __syncthreads();

    ull accA[16], accB[16];
#pragma unroll
    for (int i = 0; i < 16; i++) { accA[i] = 0ull; accB[i] = 0ull; }

    const float* WA = W1 + t;     // stride 128
    const float* WB = resW + t;   // stride 128

#pragma unroll 2
    for (int k = 0; k < 128; k++) {
        const ull wa = pack2(WA[k * 128]);
        const ull wb = pack2(WB[k * 128]);
        const ulonglong2* xp = (const ulonglong2*)(xs + k * 36);
#pragma unroll
        for (int i = 0; i < 8; i++) {
            const ulonglong2 xv = xp[i];
            fma2(accA[2 * i],     xv.x, wa);
            fma2(accA[2 * i + 1], xv.y, wa);
            fma2(accB[2 * i],     xv.x, wb);
            fma2(accB[2 * i + 1], xv.y, wb);
        }
    }

    // epilogue
    const ull asp = pack2(att_src[t]);   // (8,16) row-major: head=t>>4
    const ull adp = pack2(att_dst[t]);
    const ull bbp = pack2(res_b[t]);
    const int head = t >> 4;

#pragma unroll
    for (int i = 0; i < 16; i++) {
        const int gr = row0 + 2 * i;
        float lo, hi;
        unpack2(accA[i], lo, hi);
        g_h1[gr * HID + t]       = lo;
        g_h1[(gr + 1) * HID + t] = hi;
        g_num1[gr * HID + t]       = 0.f;
        g_num1[(gr + 1) * HID + t] = 0.f;

        // attention scalars: reduce over the 16 cols of this head
        ull vs = mul2(accA[i], asp);
        ull vd = mul2(accA[i], adp);
#pragma unroll
        for (int o = 8; o; o >>= 1) {
            vs = add2(vs, shfl_xor64(vs, o));
            vd = add2(vd, shfl_xor64(vd, o));
        }
        if ((t & 15) == 0) {
            float s0, s1, d0, d1;
            unpack2(vs, s0, s1); unpack2(vd, d0, d1);
            g_as1[gr * H1 + head]       = s0;
            g_as1[(gr + 1) * H1 + head] = s1;
            g_ad1[gr * H1 + head]       = d0;
            g_ad1[(gr + 1) * H1 + head] = d1;
        }

        ull rb = add2(accB[i], bbp);
        unpack2(rb, lo, hi);
        g_res1[gr * HID + t]       = lo;
        g_res1[(gr + 1) * HID + t] = hi;
    }

    if (t < 8) {
#pragma unroll 4
        for (int r = 0; r < 32; r++)
            g_den1[(row0 + r) * H1 + t] = 0.f;
    }
}

// ---------------- Layer 1 edge pass (single fused pass, no segment-max) -----
__global__ void k_edge1(const int* __restrict__ ei, int E)
{
    const int gw   = (blockIdx.x * blockDim.x + threadIdx.x) >> 5;
    const int lane = threadIdx.x & 31;
    if (gw >= E + NNODES) return;

    int s, d;
    load_edge(ei, E, gw, s, d);

    const int h = lane & 7;
    float l = g_as1[s * H1 + h] + g_ad1[d * H1 + h];
    l = (l > 0.f) ? l : NEG * l;
    const float ew = __expf(l);

    if (lane < 8) atomicAdd(&g_den1[d * H1 + lane], ew);

    const float w = __shfl_sync(0xffffffffu, ew, lane >> 2); // head of this float4

    float4 v = ((const float4*)(g_h1 + (size_t)s * HID))[lane];
    float4 m; m.x = v.x * w; m.y = v.y * w; m.z = v.z * w; m.w = v.w * w;
    atomicAdd(((float4*)(g_num1 + (size_t)d * HID)) + lane, m);
}

// ---------------- Layer 2 node GEMM (f32x2), fused with layer-1 finalize -----
// 64 threads, 32 rows. Thread t<40 owns W2 col t AND res2W col t (dual-col ->
// 4:1 FFMA2:LDS ratio with LDS.128). sred aliases xs after the main loop.
__global__ void __launch_bounds__(64) k_gemm2(
        const float* __restrict__ W2,
        const float* __restrict__ res2W,
        const float* __restrict__ res2_b,
        const float* __restrict__ att_src2,
        const float* __restrict__ att_dst2,
        const float* __restrict__ bias1)
{
    __shared__ __align__(16) float xs[128 * 36];   // [c][36]; reused as sred
    const int row0 = blockIdx.x * 32;
    const int t = threadIdx.x;

    // fused layer-1 finalize: h[n][c] = elu(num1/den1 + b1) + res1
    for (int idx = t; idx < 32 * 128; idx += 64) {
        const int r = idx >> 7, c = idx & 127;
        const int n = row0 + r;
        const float den = g_den1[n * H1 + (c >> 4)];
        float v = __fdividef(g_num1[n * HID + c], den) + bias1[c];
        v = (v > 0.f) ? v : (__expf(v) - 1.f);
        xs[c * 36 + r] = v + g_res1[n * HID + c];
    }
    __syncthreads();

    ull accA[16], accB[16];
#pragma unroll
    for (int i = 0; i < 16; i++) { accA[i] = 0ull; accB[i] = 0ull; }

    if (t < NCLS) {
        const float* WA = W2 + t;      // stride 40
        const float* WB = res2W + t;   // stride 40
#pragma unroll 2
        for (int k = 0; k < 128; k++) {
            const ull wa = pack2(WA[k * NCLS]);
            const ull wb = pack2(WB[k * NCLS]);
            const ulonglong2* xp = (const ulonglong2*)(xs + k * 36);
#pragma unroll
            for (int i = 0; i < 8; i++) {
                const ulonglong2 xv = xp[i];
                fma2(accA[2 * i],     xv.x, wa);
                fma2(accA[2 * i + 1], xv.y, wa);
                fma2(accB[2 * i],     xv.x, wb);
                fma2(accB[2 * i + 1], xv.y, wb);
            }
        }
    }
    __syncthreads();                    // xs reads done; safe to alias sred
    float* sred = xs;                   // [2][32][NCLS]

    if (t < NCLS) {
        const float as = att_src2[t];
        const float ad = att_dst2[t];
        const ull bp = pack2(res2_b[t]);
#pragma unroll
        for (int i = 0; i < 16; i++) {
            const int gr = row0 + 2 * i;
            float lo, hi;
            unpack2(accA[i], lo, hi);
            g_h2[gr * NCLS + t]       = lo;
            g_h2[(gr + 1) * NCLS + t] = hi;
            g_num2[gr * NCLS + t]       = 0.f;
            g_num2[(gr + 1) * NCLS + t] = 0.f;
            sred[(2 * i) * NCLS + t]     = lo * as;
            sred[(2 * i + 1) * NCLS + t] = hi * as;
            sred[32 * NCLS + (2 * i) * NCLS + t]     = lo * ad;
            sred[32 * NCLS + (2 * i + 1) * NCLS + t] = hi * ad;

            unpack2(add2(accB[i], bp), lo, hi);
            g_res2[gr * NCLS + t]       = lo;
            g_res2[(gr + 1) * NCLS + t] = hi;
        }
    }
    __syncthreads();

    if (t < 32) {
        float ss = 0.f, dd = 0.f;
#pragma unroll 8
        for (int c = 0; c < NCLS; c++) {
            ss += sred[t * NCLS + c];
            dd += sred[32 * NCLS + t * NCLS + c];
        }
        g_as2[row0 + t] = ss;
        g_ad2[row0 + t] = dd;
        g_den2[row0 + t] = 0.f;
    }
}

// ---------------- Layer 2 edge pass: 3 edges per warp ------------------------
__global__ void k_edge2(const int* __restrict__ ei, int E)
{
    const int gw   = (blockIdx.x * blockDim.x + threadIdx.x) >> 5;
    const int lane = threadIdx.x & 31;
    const int grp  = lane / 10;          // 0..2 active, 3 inactive (lanes 30,31)
    const int sub  = lane - grp * 10;
    const int e    = gw * 3 + grp;
    if (grp >= 3 || e >= E + NNODES) return;

    int s, d;
    load_edge(ei, E, e, s, d);

    float l = g_as2[s] + g_ad2[d];
    l = (l > 0.f) ? l : NEG * l;
    const float w = __expf(l);

    if (sub == 0) atomicAdd(&g_den2[d], w);

    float4 v = ((const float4*)(g_h2 + (size_t)s * NCLS))[sub];
    float4 m; m.x = v.x * w; m.y = v.y * w; m.z = v.z * w; m.w = v.w * w;
    atomicAdd(((float4*)(g_num2 + (size_t)d * NCLS)) + sub, m);
}

// ---------------- Layer 2 finalize + log_softmax -> d_out --------------------
__global__ void k_fin2(const float* __restrict__ bias2, float* __restrict__ out)
{
    const int gw   = (blockIdx.x * blockDim.x + threadIdx.x) >> 5;
    const int lane = threadIdx.x & 31;
    if (gw >= NNODES) return;

    const float inv = 1.f / g_den2[gw];
    const int base = gw * NCLS;

    float v0 = g_num2[base + lane] * inv + bias2[lane] + g_res2[base + lane];
    float v1 = -1e30f;
    if (lane < 8)
        v1 = g_num2[base + 32 + lane] * inv + bias2[32 + lane] + g_res2[base + 32 + lane];

    float m = fmaxf(v0, v1);
#pragma unroll
    for (int o = 16; o; o >>= 1) m = fmaxf(m, __shfl_xor_sync(0xffffffffu, m, o));
    float se = __expf(v0 - m) + ((lane < 8) ? __expf(v1 - m) : 0.f);
#pragma unroll
    for (int o = 16; o; o >>= 1) se += __shfl_xor_sync(0xffffffffu, se, o);
    const float lse = m + logf(se);

    out[base + lane] = v0 - lse;
    if (lane < 8) out[base + 32 + lane] = v1 - lse;
}

// ---------------- launch ------------------------------------------------------
extern "C" void kernel_launch(void* const* d_in, const int* in_sizes, int n_in,
                              void* d_out, int out_size)
{
    const float* x   = (const float*)d_in[0];
    const int*   ei  = (const int*)d_in[1];
    const float* W1  = (const float*)d_in[2];
    const float* as1 = (const float*)d_in[3];
    const float* ad1 = (const float*)d_in[4];
    const float* b1  = (const float*)d_in[5];
    const float* W2  = (const float*)d_in[6];
    const float* as2 = (const float*)d_in[7];
    const float* ad2 = (const float*)d_in[8];
    const float* b2  = (const float*)d_in[9];
    const float* r1W = (const float*)d_in[10];
    const float* r1b = (const float*)d_in[11];
    const float* r2W = (const float*)d_in[12];
    const float* r2b = (const float*)d_in[13];

    const int E  = in_sizes[1] / 2;
    const int EE = E + NNODES;
    const int e1_blocks = (EE + 7) / 8;            // 8 edge-warps / 256-thr block
    const int e2_warps  = (EE + 2) / 3;
    const int e2_blocks = (e2_warps + 7) / 8;

    k_detect<<<1, 32>>>(ei);
    k_gemm1<<<NNODES / 32, 128>>>(x, W1, r1W, r1b, as1, ad1);
    k_edge1<<<e1_blocks, 256>>>(ei, E);
    k_gemm2<<<NNODES / 32, 64>>>(W2, r2W, r2b, as2, ad2, b1);
    k_edge2<<<e2_blocks, 256>>>(ei, E);
    k_fin2 <<<(NNODES + 7) / 8, 256>>>(b2, (float*)d_out);
}

// round 5
// speedup vs baseline: 1.3688x; 1.0500x over previous
#include <cuda_runtime.h>

#define NNODES 100000
#define NFEAT  128
#define HID    128   // 8 heads * 16
#define H1     8
#define NCLS   40
#define NEG    0.2f

typedef unsigned long long ull;

// ---------------- scratch (device globals; no runtime alloc) ----------------
__device__ __align__(16) float g_h1  [NNODES * HID];
__device__ __align__(16) float g_res1[NNODES * HID];
__device__ __align__(16) float g_as1 [NNODES * H1];
__device__ __align__(16) float g_ad1 [NNODES * H1];
__device__ __align__(16) float g_num1[NNODES * HID];
__device__ __align__(16) float g_den1[NNODES * H1];
__device__ __align__(16) float g_h2  [NNODES * NCLS];
__device__ __align__(16) float g_res2[NNODES * NCLS];
__device__ __align__(16) float g_as2 [NNODES];
__device__ __align__(16) float g_ad2 [NNODES];
__device__ __align__(16) float g_num2[NNODES * NCLS];
__device__ __align__(16) float g_den2[NNODES];
__device__ int g_is64;

// ---------------- f32x2 helpers ----------------------------------------------
__device__ __forceinline__ ull pack2(float v) {
    ull r; asm("mov.b64 %0, {%1,%1};" : "=l"(r) : "f"(v)); return r;
}
__device__ __forceinline__ void unpack2(ull v, float& lo, float& hi) {
    asm("mov.b64 {%0,%1}, %2;" : "=f"(lo), "=f"(hi) : "l"(v));
}
__device__ __forceinline__ void fma2(ull& acc, ull a, ull b) {
    asm("fma.rn.f32x2 %0, %1, %2, %0;" : "+l"(acc) : "l"(a), "l"(b));
}
__device__ __forceinline__ ull mul2(ull a, ull b) {
    ull c; asm("mul.rn.f32x2 %0, %1, %2;" : "=l"(c) : "l"(a), "l"(b)); return c;
}
__device__ __forceinline__ ull add2(ull a, ull b) {
    ull c; asm("add.rn.f32x2 %0, %1, %2;" : "=l"(c) : "l"(a), "l"(b)); return c;
}
__device__ __forceinline__ ull shfl_xor64(ull v, int o) {
    double d = __longlong_as_double((long long)v);
    d = __shfl_xor_sync(0xffffffffu, d, o);
    return (ull)__double_as_longlong(d);
}

// ---------------- edge_index dtype detection ---------------------------------
__global__ void k_detect(const int* __restrict__ ei32)
{
    if (threadIdx.x == 0 && blockIdx.x == 0) {
        long long s = 0;
        for (int i = 1; i < 128; i += 2) s += ei32[i];
        g_is64 = (s == 0) ? 1 : 0;
    }
}

__device__ __forceinline__ void load_edge(const int* __restrict__ ei, int E,
                                          int gw, int& s, int& d)
{
    if (gw < E) {
        if (g_is64) {
            const long long* e64 = (const long long*)ei;
            s = (int)e64[gw];
            d = (int)e64[E + gw];
        } else {
            s = ei[gw];
            d = ei[E + gw];
        }
    } else {
        s = d = gw - E;   // self loop
    }
}

// ---------------- Layer 1 node GEMM (f32x2): 32 rows x 256 cols per block ----
__global__ void __launch_bounds__(128) k_gemm1(
        const float* __restrict__ x,
        const float* __restrict__ W1,
        const float* __restrict__ resW,
        const float* __restrict__ res_b,
        const float* __restrict__ att_src,
        const float* __restrict__ att_dst)
{
    __shared__ __align__(16) float xs[128 * 36];  // [k][36] (rows 0..31, pad 4)
    const int row0 = blockIdx.x * 32;
    const int t = threadIdx.x;

#pragma unroll 4
    for (int r = 0; r < 32; r++)
        xs[t * 36 + r] = x[(row0 + r) * NFEAT + t];
    __syncthreads();

    ull accA[16], accB[16];
#pragma unroll
    for (int i = 0; i < 16; i++) { accA[i] = 0ull; accB[i] = 0ull; }

    const float* WA = W1 + t;     // stride 128
    const float* WB = resW + t;   // stride 128

#pragma unroll 2
    for (int k = 0; k < 128; k++) {
        const ull wa = pack2(WA[k * 128]);
        const ull wb = pack2(WB[k * 128]);
        const ulonglong2* xp = (const ulonglong2*)(xs + k * 36);
#pragma unroll
        for (int i = 0; i < 8; i++) {
            const ulonglong2 xv = xp[i];
            fma2(accA[2 * i],     xv.x, wa);
            fma2(accA[2 * i + 1], xv.y, wa);
            fma2(accB[2 * i],     xv.x, wb);
            fma2(accB[2 * i + 1], xv.y, wb);
        }
    }

    const ull asp = pack2(att_src[t]);   // (8,16) row-major: head=t>>4
    const ull adp = pack2(att_dst[t]);
    const ull bbp = pack2(res_b[t]);
    const int head = t >> 4;

#pragma unroll
    for (int i = 0; i < 16; i++) {
        const int gr = row0 + 2 * i;
        float lo, hi;
        unpack2(accA[i], lo, hi);
        g_h1[gr * HID + t]       = lo;
        g_h1[(gr + 1) * HID + t] = hi;
        g_num1[gr * HID + t]       = 0.f;
        g_num1[(gr + 1) * HID + t] = 0.f;

        ull vs = mul2(accA[i], asp);
        ull vd = mul2(accA[i], adp);
#pragma unroll
        for (int o = 8; o; o >>= 1) {
            vs = add2(vs, shfl_xor64(vs, o));
            vd = add2(vd, shfl_xor64(vd, o));
        }
        if ((t & 15) == 0) {
            float s0, s1, d0, d1;
            unpack2(vs, s0, s1); unpack2(vd, d0, d1);
            g_as1[gr * H1 + head]       = s0;
            g_as1[(gr + 1) * H1 + head] = s1;
            g_ad1[gr * H1 + head]       = d0;
            g_ad1[(gr + 1) * H1 + head] = d1;
        }

        ull rb = add2(accB[i], bbp);
        unpack2(rb, lo, hi);
        g_res1[gr * HID + t]       = lo;
        g_res1[(gr + 1) * HID + t] = hi;
    }

    if (t < 8) {
#pragma unroll 4
        for (int r = 0; r < 32; r++)
            g_den1[(row0 + r) * H1 + t] = 0.f;
    }
}

// ---------------- Layer 1 edge pass (single fused pass, no segment-max) -----
__global__ void k_edge1(const int* __restrict__ ei, int E)
{
    const int gw   = (blockIdx.x * blockDim.x + threadIdx.x) >> 5;
    const int lane = threadIdx.x & 31;
    if (gw >= E + NNODES) return;

    int s, d;
    load_edge(ei, E, gw, s, d);

    const int h = lane & 7;
    float l = g_as1[s * H1 + h] + g_ad1[d * H1 + h];
    l = (l > 0.f) ? l : NEG * l;
    const float ew = __expf(l);

    if (lane < 8) atomicAdd(&g_den1[d * H1 + lane], ew);

    const float w = __shfl_sync(0xffffffffu, ew, lane >> 2); // head of this float4

    float4 v = ((const float4*)(g_h1 + (size_t)s * HID))[lane];
    float4 m; m.x = v.x * w; m.y = v.y * w; m.z = v.z * w; m.w = v.w * w;
    atomicAdd(((float4*)(g_num1 + (size_t)d * HID)) + lane, m);
}

// ---------------- Layer 2 node GEMM (f32x2), fused with layer-1 finalize -----
// 160 threads = 80 cols (40 W2 + 40 res2W) x 2 row-halves of 16 rows.
// All warps fully active; LDS.128 x reads are warp-broadcast.
__global__ void __launch_bounds__(160) k_gemm2(
        const float* __restrict__ W2,
        const float* __restrict__ res2W,
        const float* __restrict__ res2_b,
        const float* __restrict__ att_src2,
        const float* __restrict__ att_dst2,
        const float* __restrict__ bias1)
{
    __shared__ __align__(16) float xs[128 * 36];   // [c][36]; reused as sred
    const int row0 = blockIdx.x * 32;
    const int t = threadIdx.x;

    // fused layer-1 finalize: h[n][c] = elu(num1/den1 + b1) + res1
    for (int idx = t; idx < 32 * 128; idx += 160) {
        const int r = idx >> 7, c = idx & 127;
        const int n = row0 + r;
        const float den = g_den1[n * H1 + (c >> 4)];
        float v = __fdividef(g_num1[n * HID + c], den) + bias1[c];
        v = (v > 0.f) ? v : (__expf(v) - 1.f);
        xs[c * 36 + r] = v + g_res1[n * HID + c];
    }
    __syncthreads();

    const int col  = t % 80;            // 0..39 -> W2, 40..79 -> res2W
    const int half = t / 80;            // 0/1 -> rows [0,16) / [16,32)

    ull acc[8];
#pragma unroll
    for (int i = 0; i < 8; i++) acc[i] = 0ull;

    const float* Wc = (col < NCLS) ? (W2 + col) : (res2W + (col - NCLS));
#pragma unroll 2
    for (int k = 0; k < 128; k++) {
        const ull w = pack2(Wc[k * NCLS]);
        const ulonglong2* xp = (const ulonglong2*)(xs + k * 36 + half * 16);
#pragma unroll
        for (int i = 0; i < 4; i++) {
            const ulonglong2 xv = xp[i];
            fma2(acc[2 * i],     xv.x, w);
            fma2(acc[2 * i + 1], xv.y, w);
        }
    }
    __syncthreads();                    // xs reads done; alias sred
    float* sred = xs;                   // [2][32][NCLS] = 10240B

    if (col < NCLS) {
        const float as = att_src2[col];
        const float ad = att_dst2[col];
#pragma unroll
        for (int i = 0; i < 8; i++) {
            const int lr = half * 16 + 2 * i;
            const int gr = row0 + lr;
            float lo, hi;
            unpack2(acc[i], lo, hi);
            g_h2[gr * NCLS + col]       = lo;
            g_h2[(gr + 1) * NCLS + col] = hi;
            g_num2[gr * NCLS + col]       = 0.f;
            g_num2[(gr + 1) * NCLS + col] = 0.f;
            sred[lr * NCLS + col]       = lo * as;
            sred[(lr + 1) * NCLS + col] = hi * as;
            sred[32 * NCLS + lr * NCLS + col]       = lo * ad;
            sred[32 * NCLS + (lr + 1) * NCLS + col] = hi * ad;
        }
    } else {
        const int jc = col - NCLS;
        const ull bp = pack2(res2_b[jc]);
#pragma unroll
        for (int i = 0; i < 8; i++) {
            const int gr = row0 + half * 16 + 2 * i;
            float lo, hi;
            unpack2(add2(acc[i], bp), lo, hi);
            g_res2[gr * NCLS + jc]       = lo;
            g_res2[(gr + 1) * NCLS + jc] = hi;
        }
    }
    __syncthreads();

    if (t < 32) {
        float ss = 0.f, dd = 0.f;
#pragma unroll 8
        for (int c = 0; c < NCLS; c++) {
            ss += sred[t * NCLS + c];
            dd += sred[32 * NCLS + t * NCLS + c];
        }
        g_as2[row0 + t] = ss;
        g_ad2[row0 + t] = dd;
        g_den2[row0 + t] = 0.f;
    }
}

// ---------------- Layer 2 edge pass: 3 edges per warp ------------------------
__global__ void k_edge2(const int* __restrict__ ei, int E)
{
    const int gw   = (blockIdx.x * blockDim.x + threadIdx.x) >> 5;
    const int lane = threadIdx.x & 31;
    const int grp  = lane / 10;          // 0..2 active; lanes 30,31 idle
    const int sub  = lane - grp * 10;
    const int e    = gw * 3 + grp;
    if (grp >= 3 || e >= E + NNODES) return;

    int s, d;
    load_edge(ei, E, e, s, d);

    float l = g_as2[s] + g_ad2[d];
    l = (l > 0.f) ? l : NEG * l;
    const float w = __expf(l);

    if (sub == 0) atomicAdd(&g_den2[d], w);

    float4 v = ((const float4*)(g_h2 + (size_t)s * NCLS))[sub];
    float4 m; m.x = v.x * w; m.y = v.y * w; m.z = v.z * w; m.w = v.w * w;
    atomicAdd(((float4*)(g_num2 + (size_t)d * NCLS)) + sub, m);
}

// ---------------- Layer 2 finalize + log_softmax -> d_out --------------------
__global__ void k_fin2(const float* __restrict__ bias2, float* __restrict__ out)
{
    const int gw   = (blockIdx.x * blockDim.x + threadIdx.x) >> 5;
    const int lane = threadIdx.x & 31;
    if (gw >= NNODES) return;

    const float inv = 1.f / g_den2[gw];
    const int base = gw * NCLS;

    float v0 = g_num2[base + lane] * inv + bias2[lane] + g_res2[base + lane];
    float v1 = -1e30f;
    if (lane < 8)
        v1 = g_num2[base + 32 + lane] * inv + bias2[32 + lane] + g_res2[base + 32 + lane];

    float m = fmaxf(v0, v1);
#pragma unroll
    for (int o = 16; o; o >>= 1) m = fmaxf(m, __shfl_xor_sync(0xffffffffu, m, o));
    float se = __expf(v0 - m) + ((lane < 8) ? __expf(v1 - m) : 0.f);
#pragma unroll
    for (int o = 16; o; o >>= 1) se += __shfl_xor_sync(0xffffffffu, se, o);
    const float lse = m + logf(se);

    out[base + lane] = v0 - lse;
    if (lane < 8) out[base + 32 + lane] = v1 - lse;
}

// ---------------- launch ------------------------------------------------------
extern "C" void kernel_launch(void* const* d_in, const int* in_sizes, int n_in,
                              void* d_out, int out_size)
{
    const float* x   = (const float*)d_in[0];
    const int*   ei  = (const int*)d_in[1];
    const float* W1  = (const float*)d_in[2];
    const float* as1 = (const float*)d_in[3];
    const float* ad1 = (const float*)d_in[4];
    const float* b1  = (const float*)d_in[5];
    const float* W2  = (const float*)d_in[6];
    const float* as2 = (const float*)d_in[7];
    const float* ad2 = (const float*)d_in[8];
    const float* b2  = (const float*)d_in[9];
    const float* r1W = (const float*)d_in[10];
    const float* r1b = (const float*)d_in[11];
    const float* r2W = (const float*)d_in[12];
    const float* r2b = (const float*)d_in[13];

    const int E  = in_sizes[1] / 2;
    const int EE = E + NNODES;
    const int e1_blocks = (EE + 7) / 8;            // 8 edge-warps / 256-thr block
    const int e2_warps  = (EE + 2) / 3;
    const int e2_blocks = (e2_warps + 7) / 8;

    k_detect<<<1, 32>>>(ei);
    k_gemm1<<<NNODES / 32, 128>>>(x, W1, r1W, r1b, as1, ad1);
    k_edge1<<<e1_blocks, 256>>>(ei, E);
    k_gemm2<<<NNODES / 32, 160>>>(W2, r2W, r2b, as2, ad2, b1);
    k_edge2<<<e2_blocks, 256>>>(ei, E);
    k_fin2 <<<(NNODES + 7) / 8, 256>>>(b2, (float*)d_out);
}

// round 6
// speedup vs baseline: 1.6926x; 1.2366x over previous
#include <cuda_runtime.h>

#define NNODES 100000
#define NFEAT  128
#define HID    128   // 8 heads * 16
#define H1     8
#define NCLS   40
#define NEG    0.2f
#define EMAX   1664000

typedef unsigned long long ull;

// ---------------- scratch (device globals; no runtime alloc) ----------------
__device__ __align__(16) float g_h1  [NNODES * HID];
__device__ __align__(16) float g_res1[NNODES * HID];
__device__ __align__(16) float g_as1 [NNODES * H1];
__device__ __align__(16) float g_ad1 [NNODES * H1];
__device__ __align__(16) float g_h   [NNODES * HID];
__device__ __align__(16) float g_h2  [NNODES * NCLS];
__device__ __align__(16) float g_res2[NNODES * NCLS];
__device__ __align__(16) float g_as2 [NNODES];
__device__ __align__(16) float g_ad2 [NNODES];
__device__ int g_deg[NNODES];
__device__ int g_off[NNODES + 1];
__device__ int g_cur[NNODES];
__device__ int g_csr[EMAX];
__device__ int g_is64;

// ---------------- f32x2 helpers ----------------------------------------------
__device__ __forceinline__ ull pack2(float v) {
    ull r; asm("mov.b64 %0, {%1,%1};" : "=l"(r) : "f"(v)); return r;
}
__device__ __forceinline__ void unpack2(ull v, float& lo, float& hi) {
    asm("mov.b64 {%0,%1}, %2;" : "=f"(lo), "=f"(hi) : "l"(v));
}
__device__ __forceinline__ void fma2(ull& acc, ull a, ull b) {
    asm("fma.rn.f32x2 %0, %1, %2, %0;" : "+l"(acc) : "l"(a), "l"(b));
}
__device__ __forceinline__ ull mul2(ull a, ull b) {
    ull c; asm("mul.rn.f32x2 %0, %1, %2;" : "=l"(c) : "l"(a), "l"(b)); return c;
}
__device__ __forceinline__ ull add2(ull a, ull b) {
    ull c; asm("add.rn.f32x2 %0, %1, %2;" : "=l"(c) : "l"(a), "l"(b)); return c;
}
__device__ __forceinline__ ull shfl_xor64(ull v, int o) {
    double d = __longlong_as_double((long long)v);
    d = __shfl_xor_sync(0xffffffffu, d, o);
    return (ull)__double_as_longlong(d);
}

// ---------------- edge_index dtype detection ---------------------------------
__global__ void k_detect(const int* __restrict__ ei32)
{
    if (threadIdx.x == 0 && blockIdx.x == 0) {
        long long s = 0;
        for (int i = 1; i < 128; i += 2) s += ei32[i];
        g_is64 = (s == 0) ? 1 : 0;
    }
}

__device__ __forceinline__ int edge_dst(const int* __restrict__ ei, int E, int e)
{
    return g_is64 ? (int)((const long long*)ei)[E + e] : ei[E + e];
}
__device__ __forceinline__ int edge_src(const int* __restrict__ ei, int E, int e)
{
    return g_is64 ? (int)((const long long*)ei)[e] : ei[e];
}

// ---------------- CSR build ----------------------------------------------------
__global__ void k_zero()
{
    const int i = blockIdx.x * blockDim.x + threadIdx.x;
    if (i < NNODES) { g_deg[i] = 0; g_cur[i] = 0; }
}

__global__ void k_hist(const int* __restrict__ ei, int E)
{
    const int e = blockIdx.x * blockDim.x + threadIdx.x;
    if (e >= E) return;
    atomicAdd(&g_deg[edge_dst(ei, E, e)], 1);
}

// single-block exclusive scan over g_deg -> g_off
__global__ void __launch_bounds__(1024) k_scan()
{
    __shared__ int wsum[32];
    __shared__ int carry_s;
    const int t = threadIdx.x, lane = t & 31, wid = t >> 5;
    if (t == 0) carry_s = 0;
    __syncthreads();

    for (int base = 0; base < NNODES; base += 1024) {
        const int idx = base + t;
        const int v = (idx < NNODES) ? g_deg[idx] : 0;
        int inc = v;
#pragma unroll
        for (int o = 1; o < 32; o <<= 1) {
            int n = __shfl_up_sync(0xffffffffu, inc, o);
            if (lane >= o) inc += n;
        }
        if (lane == 31) wsum[wid] = inc;
        __syncthreads();
        if (wid == 0) {
            int s = wsum[lane];
#pragma unroll
            for (int o = 1; o < 32; o <<= 1) {
                int n = __shfl_up_sync(0xffffffffu, s, o);
                if (lane >= o) s += n;
            }
            wsum[lane] = s;
        }
        __syncthreads();
        const int pre = (wid > 0) ? wsum[wid - 1] : 0;
        const int carry = carry_s;
        if (idx < NNODES) g_off[idx] = carry + pre + inc - v;
        __syncthreads();
        if (t == 1023) carry_s = carry + pre + inc;
        __syncthreads();
    }
    if (t == 0) g_off[NNODES] = carry_s;
}

__global__ void k_scatter(const int* __restrict__ ei, int E)
{
    const int e = blockIdx.x * blockDim.x + threadIdx.x;
    if (e >= E) return;
    const int d = edge_dst(ei, E, e);
    const int s = edge_src(ei, E, e);
    const int pos = g_off[d] + atomicAdd(&g_cur[d], 1);
    g_csr[pos] = s;
}

// ---------------- Layer 1 node GEMM (f32x2): 32 rows x 256 cols per block ----
__global__ void __launch_bounds__(128) k_gemm1(
        const float* __restrict__ x,
        const float* __restrict__ W1,
        const float* __restrict__ resW,
        const float* __restrict__ res_b,
        const float* __restrict__ att_src,
        const float* __restrict__ att_dst)
{
    __shared__ __align__(16) float xs[128 * 36];  // [k][36]
    const int row0 = blockIdx.x * 32;
    const int t = threadIdx.x;

#pragma unroll 4
    for (int r = 0; r < 32; r++)
        xs[t * 36 + r] = x[(row0 + r) * NFEAT + t];
    __syncthreads();

    ull accA[16], accB[16];
#pragma unroll
    for (int i = 0; i < 16; i++) { accA[i] = 0ull; accB[i] = 0ull; }

    const float* WA = W1 + t;     // stride 128
    const float* WB = resW + t;   // stride 128

#pragma unroll 2
    for (int k = 0; k < 128; k++) {
        const ull wa = pack2(WA[k * 128]);
        const ull wb = pack2(WB[k * 128]);
        const ulonglong2* xp = (const ulonglong2*)(xs + k * 36);
#pragma unroll
        for (int i = 0; i < 8; i++) {
            const ulonglong2 xv = xp[i];
            fma2(accA[2 * i],     xv.x, wa);
            fma2(accA[2 * i + 1], xv.y, wa);
            fma2(accB[2 * i],     xv.x, wb);
            fma2(accB[2 * i + 1], xv.y, wb);
        }
    }

    const ull asp = pack2(att_src[t]);   // (8,16) row-major: head=t>>4
    const ull adp = pack2(att_dst[t]);
    const ull bbp = pack2(res_b[t]);
    const int head = t >> 4;

#pragma unroll
    for (int i = 0; i < 16; i++) {
        const int gr = row0 + 2 * i;
        float lo, hi;
        unpack2(accA[i], lo, hi);
        g_h1[gr * HID + t]       = lo;
        g_h1[(gr + 1) * HID + t] = hi;

        ull vs = mul2(accA[i], asp);
        ull vd = mul2(accA[i], adp);
#pragma unroll
        for (int o = 8; o; o >>= 1) {
            vs = add2(vs, shfl_xor64(vs, o));
            vd = add2(vd, shfl_xor64(vd, o));
        }
        if ((t & 15) == 0) {
            float s0, s1, d0, d1;
            unpack2(vs, s0, s1); unpack2(vd, d0, d1);
            g_as1[gr * H1 + head]       = s0;
            g_as1[(gr + 1) * H1 + head] = s1;
            g_ad1[gr * H1 + head]       = d0;
            g_ad1[(gr + 1) * H1 + head] = d1;
        }

        ull rb = add2(accB[i], bbp);
        unpack2(rb, lo, hi);
        g_res1[gr * HID + t]       = lo;
        g_res1[(gr + 1) * HID + t] = hi;
    }
}

// ---------------- Layer 1 aggregation: warp per dst node, CSR gather ---------
// Register accumulation (no atomics), fused finalize -> g_h.
__global__ void k_edge1agg(const float* __restrict__ bias1)
{
    const int d    = (blockIdx.x * blockDim.x + threadIdx.x) >> 5;
    const int lane = threadIdx.x & 31;
    if (d >= NNODES) return;

    const int h = lane & 7;
    const float ad = g_ad1[d * H1 + h];

    // self loop
    float l = g_as1[d * H1 + h] + ad;
    l = (l > 0.f) ? l : NEG * l;
    float den = __expf(l);
    float w = __shfl_sync(0xffffffffu, den, lane >> 2);
    float4 v = ((const float4*)(g_h1 + (size_t)d * HID))[lane];
    float4 acc; acc.x = v.x * w; acc.y = v.y * w; acc.z = v.z * w; acc.w = v.w * w;

    const int end = g_off[d + 1];
    int e = g_off[d];
    int s = (e < end) ? g_csr[e] : 0;
    for (; e < end; e++) {
        const int snext = (e + 1 < end) ? g_csr[e + 1] : 0;
        float ls = g_as1[s * H1 + h] + ad;
        ls = (ls > 0.f) ? ls : NEG * ls;
        const float ew = __expf(ls);
        den += ew;
        const float ww = __shfl_sync(0xffffffffu, ew, lane >> 2);
        const float4 u = ((const float4*)(g_h1 + (size_t)s * HID))[lane];
        acc.x += u.x * ww; acc.y += u.y * ww;
        acc.z += u.z * ww; acc.w += u.w * ww;
        s = snext;
    }

    const float dh  = __shfl_sync(0xffffffffu, den, lane >> 2);
    const float inv = __fdividef(1.f, dh);
    const float4 b = ((const float4*)bias1)[lane];
    const float4 r = ((const float4*)(g_res1 + (size_t)d * HID))[lane];
    float4 o;
    float t0;
    t0 = acc.x * inv + b.x; o.x = ((t0 > 0.f) ? t0 : (__expf(t0) - 1.f)) + r.x;
    t0 = acc.y * inv + b.y; o.y = ((t0 > 0.f) ? t0 : (__expf(t0) - 1.f)) + r.y;
    t0 = acc.z * inv + b.z; o.z = ((t0 > 0.f) ? t0 : (__expf(t0) - 1.f)) + r.z;
    t0 = acc.w * inv + b.w; o.w = ((t0 > 0.f) ? t0 : (__expf(t0) - 1.f)) + r.w;
    ((float4*)(g_h + (size_t)d * HID))[lane] = o;
}

// ---------------- Layer 2 node GEMM (f32x2): reads g_h -----------------------
// 160 threads = 80 cols (40 W2 + 40 res2W) x 2 row-halves of 16 rows.
__global__ void __launch_bounds__(160) k_gemm2(
        const float* __restrict__ W2,
        const float* __restrict__ res2W,
        const float* __restrict__ res2_b,
        const float* __restrict__ att_src2,
        const float* __restrict__ att_dst2)
{
    __shared__ __align__(16) float xs[128 * 36];   // [c][36]; reused as sred
    const int row0 = blockIdx.x * 32;
    const int t = threadIdx.x;

    for (int idx = t; idx < 32 * 128; idx += 160) {
        const int r = idx >> 7, c = idx & 127;
        xs[c * 36 + r] = g_h[(size_t)(row0 + r) * HID + c];
    }
    __syncthreads();

    const int col  = t % 80;            // 0..39 -> W2, 40..79 -> res2W
    const int half = t / 80;            // 0/1 -> rows [0,16) / [16,32)

    ull acc[8];
#pragma unroll
    for (int i = 0; i < 8; i++) acc[i] = 0ull;

    const float* Wc = (col < NCLS) ? (W2 + col) : (res2W + (col - NCLS));
#pragma unroll 2
    for (int k = 0; k < 128; k++) {
        const ull w = pack2(Wc[k * NCLS]);
        const ulonglong2* xp = (const ulonglong2*)(xs + k * 36 + half * 16);
#pragma unroll
        for (int i = 0; i < 4; i++) {
            const ulonglong2 xv = xp[i];
            fma2(acc[2 * i],     xv.x, w);
            fma2(acc[2 * i + 1], xv.y, w);
        }
    }
    __syncthreads();                    // xs reads done; alias sred
    float* sred = xs;                   // [2][32][NCLS]

    if (col < NCLS) {
        const float as = att_src2[col];
        const float ad = att_dst2[col];
#pragma unroll
        for (int i = 0; i < 8; i++) {
            const int lr = half * 16 + 2 * i;
            const int gr = row0 + lr;
            float lo, hi;
            unpack2(acc[i], lo, hi);
            g_h2[gr * NCLS + col]       = lo;
            g_h2[(gr + 1) * NCLS + col] = hi;
            sred[lr * NCLS + col]       = lo * as;
            sred[(lr + 1) * NCLS + col] = hi * as;
            sred[32 * NCLS + lr * NCLS + col]       = lo * ad;
            sred[32 * NCLS + (lr + 1) * NCLS + col] = hi * ad;
        }
    } else {
        const int jc = col - NCLS;
        const ull bp = pack2(res2_b[jc]);
#pragma unroll
        for (int i = 0; i < 8; i++) {
            const int gr = row0 + half * 16 + 2 * i;
            float lo, hi;
            unpack2(add2(acc[i], bp), lo, hi);
            g_res2[gr * NCLS + jc]       = lo;
            g_res2[(gr + 1) * NCLS + jc] = hi;
        }
    }
    __syncthreads();

    if (t < 32) {
        float ss = 0.f, dd = 0.f;
#pragma unroll 8
        for (int c = 0; c < NCLS; c++) {
            ss += sred[t * NCLS + c];
            dd += sred[32 * NCLS + t * NCLS + c];
        }
        g_as2[row0 + t] = ss;
        g_ad2[row0 + t] = dd;
    }
}

// ---------------- Layer 2 aggregation + log_softmax: warp per dst node -------
// 3 edge-groups of 10 lanes; register accumulation; fused finalize -> d_out.
__global__ void k_edge2fin(const float* __restrict__ bias2,
                           float* __restrict__ out)
{
    const int d    = (blockIdx.x * blockDim.x + threadIdx.x) >> 5;
    const int lane = threadIdx.x & 31;
    if (d >= NNODES) return;

    const int grp = lane / 10;           // 0..2 active; 3 = lanes 30,31 (idle)
    const int sub = lane - grp * 10;
    const float ad = g_ad2[d];

    float den = 0.f;
    float4 acc; acc.x = acc.y = acc.z = acc.w = 0.f;

    if (grp == 0) {                      // self loop handled by group 0
        float l = g_as2[d] + ad;
        l = (l > 0.f) ? l : NEG * l;
        const float w = __expf(l);
        den = w;
        const float4 v = ((const float4*)(g_h2 + (size_t)d * NCLS))[sub];
        acc.x = v.x * w; acc.y = v.y * w; acc.z = v.z * w; acc.w = v.w * w;
    }

    if (grp < 3) {
        const int end = g_off[d + 1];
        for (int e = g_off[d] + grp; e < end; e += 3) {
            const int s = g_csr[e];
            float l = g_as2[s] + ad;
            l = (l > 0.f) ? l : NEG * l;
            const float w = __expf(l);
            den += w;
            const float4 v = ((const float4*)(g_h2 + (size_t)s * NCLS))[sub];
            acc.x += v.x * w; acc.y += v.y * w;
            acc.z += v.z * w; acc.w += v.w * w;
        }
    }

    // combine the 3 groups (results valid on lanes 0..9)
    const unsigned FULL = 0xffffffffu;
    float den_t = den + __shfl_sync(FULL, den, lane + 10)
                      + __shfl_sync(FULL, den, lane + 20);
    float ax = acc.x + __shfl_sync(FULL, acc.x, lane + 10) + __shfl_sync(FULL, acc.x, lane + 20);
    float ay = acc.y + __shfl_sync(FULL, acc.y, lane + 10) + __shfl_sync(FULL, acc.y, lane + 20);
    float az = acc.z + __shfl_sync(FULL, acc.z, lane + 10) + __shfl_sync(FULL, acc.z, lane + 20);
    float aw = acc.w + __shfl_sync(FULL, acc.w, lane + 10) + __shfl_sync(FULL, acc.w, lane + 20);

    const float inv = __fdividef(1.f, den_t);
    const float4 b = ((const float4*)bias2)[sub];
    const float4 r = ((const float4*)(g_res2 + (size_t)d * NCLS))[sub];
    float4 val;
    val.x = ax * inv + b.x + r.x;
    val.y = ay * inv + b.y + r.y;
    val.z = az * inv + b.z + r.z;
    val.w = aw * inv + b.w + r.w;

    // log_softmax over the 40 values (lanes 0..9 x 4 comps)
    float m = (lane < 10) ? fmaxf(fmaxf(val.x, val.y), fmaxf(val.z, val.w)) : -3.4e38f;
#pragma unroll
    for (int o = 16; o; o >>= 1) m = fmaxf(m, __shfl_xor_sync(FULL, m, o));
    float se = (lane < 10)
        ? (__expf(val.x - m) + __expf(val.y - m) + __expf(val.z - m) + __expf(val.w - m))
        : 0.f;
#pragma unroll
    for (int o = 16; o; o >>= 1) se += __shfl_xor_sync(FULL, se, o);
    const float lse = m + logf(se);

    if (lane < 10) {
        float4 o4;
        o4.x = val.x - lse; o4.y = val.y - lse;
        o4.z = val.z - lse; o4.w = val.w - lse;
        ((float4*)(out + (size_t)d * NCLS))[sub] = o4;
    }
}

// ---------------- launch ------------------------------------------------------
extern "C" void kernel_launch(void* const* d_in, const int* in_sizes, int n_in,
                              void* d_out, int out_size)
{
    const float* x   = (const float*)d_in[0];
    const int*   ei  = (const int*)d_in[1];
    const float* W1  = (const float*)d_in[2];
    const float* as1 = (const float*)d_in[3];
    const float* ad1 = (const float*)d_in[4];
    const float* b1  = (const float*)d_in[5];
    const float* W2  = (const float*)d_in[6];
    const float* as2 = (const float*)d_in[7];
    const float* ad2 = (const float*)d_in[8];
    const float* b2  = (const float*)d_in[9];
    const float* r1W = (const float*)d_in[10];
    const float* r1b = (const float*)d_in[11];
    const float* r2W = (const float*)d_in[12];
    const float* r2b = (const float*)d_in[13];

    const int E = in_sizes[1] / 2;

    k_detect <<<1, 32>>>(ei);
    k_zero   <<<(NNODES + 255) / 256, 256>>>();
    k_hist   <<<(E + 255) / 256, 256>>>(ei, E);
    k_scan   <<<1, 1024>>>();
    k_scatter<<<(E + 255) / 256, 256>>>(ei, E);
    k_gemm1  <<<NNODES / 32, 128>>>(x, W1, r1W, r1b, as1, ad1);
    k_edge1agg<<<(NNODES + 7) / 8, 256>>>(b1);
    k_gemm2  <<<NNODES / 32, 160>>>(W2, r2W, r2b, as2, ad2);
    k_edge2fin<<<(NNODES + 7) / 8, 256>>>(b2, (float*)d_out);
}

// round 7
// speedup vs baseline: 1.9096x; 1.1282x over previous
#include <cuda_runtime.h>

#define NNODES 100000
#define NFEAT  128
#define HID    128   // 8 heads * 16
#define H1     8
#define NCLS   40
#define NEG    0.2f
#define EMAX   1664000
#define SCAN_BLKS 98   // ceil(100000/1024)

typedef unsigned long long ull;

// ---------------- scratch (device globals; no runtime alloc) ----------------
__device__ __align__(16) float g_h1  [NNODES * HID];
__device__ __align__(16) float g_res1[NNODES * HID];
__device__ __align__(16) float g_as1 [NNODES * H1];
__device__ __align__(16) float g_ad1 [NNODES * H1];
__device__ __align__(16) float g_h   [NNODES * HID];
__device__ __align__(16) float g_h2  [NNODES * NCLS];
__device__ __align__(16) float g_res2[NNODES * NCLS];
__device__ __align__(16) float g_as2 [NNODES];
__device__ __align__(16) float g_ad2 [NNODES];
__device__ int g_deg[NNODES];
__device__ int g_off[NNODES + 1];
__device__ int g_cur[NNODES];
__device__ int g_csr[EMAX];
__device__ int g_bsum[128];
__device__ int g_is64;

// ---------------- f32x2 helpers ----------------------------------------------
__device__ __forceinline__ ull pack2(float v) {
    ull r; asm("mov.b64 %0, {%1,%1};" : "=l"(r) : "f"(v)); return r;
}
__device__ __forceinline__ void unpack2(ull v, float& lo, float& hi) {
    asm("mov.b64 {%0,%1}, %2;" : "=f"(lo), "=f"(hi) : "l"(v));
}
__device__ __forceinline__ void fma2(ull& acc, ull a, ull b) {
    asm("fma.rn.f32x2 %0, %1, %2, %0;" : "+l"(acc) : "l"(a), "l"(b));
}
__device__ __forceinline__ ull mul2(ull a, ull b) {
    ull c; asm("mul.rn.f32x2 %0, %1, %2;" : "=l"(c) : "l"(a), "l"(b)); return c;
}
__device__ __forceinline__ ull add2(ull a, ull b) {
    ull c; asm("add.rn.f32x2 %0, %1, %2;" : "=l"(c) : "l"(a), "l"(b)); return c;
}
__device__ __forceinline__ ull shfl_xor64(ull v, int o) {
    double d = __longlong_as_double((long long)v);
    d = __shfl_xor_sync(0xffffffffu, d, o);
    return (ull)__double_as_longlong(d);
}

// ---------------- edge_index dtype detection ---------------------------------
__global__ void k_detect(const int* __restrict__ ei32)
{
    if (threadIdx.x == 0 && blockIdx.x == 0) {
        long long s = 0;
        for (int i = 1; i < 128; i += 2) s += ei32[i];
        g_is64 = (s == 0) ? 1 : 0;
    }
}

__device__ __forceinline__ int edge_dst(const int* __restrict__ ei, int E, int e)
{
    return g_is64 ? (int)((const long long*)ei)[E + e] : ei[E + e];
}
__device__ __forceinline__ int edge_src(const int* __restrict__ ei, int E, int e)
{
    return g_is64 ? (int)((const long long*)ei)[e] : ei[e];
}

// ---------------- CSR build ----------------------------------------------------
__global__ void k_zero()
{
    const int i = blockIdx.x * blockDim.x + threadIdx.x;
    if (i < NNODES) { g_deg[i] = 0; g_cur[i] = 0; }
}

__global__ void k_hist(const int* __restrict__ ei, int E)
{
    const int e = blockIdx.x * blockDim.x + threadIdx.x;
    if (e >= E) return;
    atomicAdd(&g_deg[edge_dst(ei, E, e)], 1);
}

// phase A: per-block exclusive scan; block totals -> g_bsum
__global__ void __launch_bounds__(1024) k_scanA()
{
    __shared__ int wsum[32];
    const int t = threadIdx.x, lane = t & 31, wid = t >> 5;
    const int idx = blockIdx.x * 1024 + t;
    const int v = (idx < NNODES) ? g_deg[idx] : 0;

    int inc = v;
#pragma unroll
    for (int o = 1; o < 32; o <<= 1) {
        int n = __shfl_up_sync(0xffffffffu, inc, o);
        if (lane >= o) inc += n;
    }
    if (lane == 31) wsum[wid] = inc;
    __syncthreads();
    if (wid == 0) {
        int s = wsum[lane];
#pragma unroll
        for (int o = 1; o < 32; o <<= 1) {
            int n = __shfl_up_sync(0xffffffffu, s, o);
            if (lane >= o) s += n;
        }
        wsum[lane] = s;
    }
    __syncthreads();
    const int pre = (wid > 0) ? wsum[wid - 1] : 0;
    if (idx < NNODES) g_off[idx] = pre + inc - v;      // block-local exclusive
    if (t == 1023) g_bsum[blockIdx.x] = pre + inc;     // block total
}

// phase B: scan the block totals (1 block, 128 threads)
__global__ void k_scanB()
{
    __shared__ int sh[128];
    const int t = threadIdx.x;
    const int v = (t < SCAN_BLKS) ? g_bsum[t] : 0;
    sh[t] = v;
    __syncthreads();
#pragma unroll
    for (int o = 1; o < 128; o <<= 1) {
        const int n = (t >= o) ? sh[t - o] : 0;
        __syncthreads();
        sh[t] += n;
        __syncthreads();
    }
    g_bsum[t] = sh[t] - v;                  // exclusive
    if (t == 127) g_off[NNODES] = sh[127];  // grand total
}

// phase C: add block offsets
__global__ void __launch_bounds__(1024) k_scanC()
{
    const int idx = blockIdx.x * 1024 + threadIdx.x;
    if (idx < NNODES) g_off[idx] += g_bsum[blockIdx.x];
}

__global__ void k_scatter(const int* __restrict__ ei, int E)
{
    const int e = blockIdx.x * blockDim.x + threadIdx.x;
    if (e >= E) return;
    const int d = edge_dst(ei, E, e);
    const int s = edge_src(ei, E, e);
    const int pos = g_off[d] + atomicAdd(&g_cur[d], 1);
    g_csr[pos] = s;
}

// ---------------- Layer 1 node GEMM (f32x2): 32 rows x 256 cols per block ----
__global__ void __launch_bounds__(128) k_gemm1(
        const float* __restrict__ x,
        const float* __restrict__ W1,
        const float* __restrict__ resW,
        const float* __restrict__ res_b,
        const float* __restrict__ att_src,
        const float* __restrict__ att_dst)
{
    __shared__ __align__(16) float xs[128 * 36];  // [k][36]
    const int row0 = blockIdx.x * 32;
    const int t = threadIdx.x;

#pragma unroll 4
    for (int r = 0; r < 32; r++)
        xs[t * 36 + r] = x[(row0 + r) * NFEAT + t];
    __syncthreads();

    ull accA[16], accB[16];
#pragma unroll
    for (int i = 0; i < 16; i++) { accA[i] = 0ull; accB[i] = 0ull; }

    const float* WA = W1 + t;     // stride 128
    const float* WB = resW + t;   // stride 128

#pragma unroll 2
    for (int k = 0; k < 128; k++) {
        const ull wa = pack2(WA[k * 128]);
        const ull wb = pack2(WB[k * 128]);
        const ulonglong2* xp = (const ulonglong2*)(xs + k * 36);
#pragma unroll
        for (int i = 0; i < 8; i++) {
            const ulonglong2 xv = xp[i];
            fma2(accA[2 * i],     xv.x, wa);
            fma2(accA[2 * i + 1], xv.y, wa);
            fma2(accB[2 * i],     xv.x, wb);
            fma2(accB[2 * i + 1], xv.y, wb);
        }
    }

    const ull asp = pack2(att_src[t]);   // (8,16) row-major: head=t>>4
    const ull adp = pack2(att_dst[t]);
    const ull bbp = pack2(res_b[t]);
    const int head = t >> 4;

#pragma unroll
    for (int i = 0; i < 16; i++) {
        const int gr = row0 + 2 * i;
        float lo, hi;
        unpack2(accA[i], lo, hi);
        g_h1[gr * HID + t]       = lo;
        g_h1[(gr + 1) * HID + t] = hi;

        ull vs = mul2(accA[i], asp);
        ull vd = mul2(accA[i], adp);
#pragma unroll
        for (int o = 8; o; o >>= 1) {
            vs = add2(vs, shfl_xor64(vs, o));
            vd = add2(vd, shfl_xor64(vd, o));
        }
        if ((t & 15) == 0) {
            float s0, s1, d0, d1;
            unpack2(vs, s0, s1); unpack2(vd, d0, d1);
            g_as1[gr * H1 + head]       = s0;
            g_as1[(gr + 1) * H1 + head] = s1;
            g_ad1[gr * H1 + head]       = d0;
            g_ad1[(gr + 1) * H1 + head] = d1;
        }

        ull rb = add2(accB[i], bbp);
        unpack2(rb, lo, hi);
        g_res1[gr * HID + t]       = lo;
        g_res1[(gr + 1) * HID + t] = hi;
    }
}

// ---------------- Layer 1 aggregation: warp per dst node, CSR gather ---------
__global__ void k_edge1agg(const float* __restrict__ bias1)
{
    const int d    = (blockIdx.x * blockDim.x + threadIdx.x) >> 5;
    const int lane = threadIdx.x & 31;
    if (d >= NNODES) return;

    const int h = lane & 7;
    const float ad = g_ad1[d * H1 + h];

    // self loop
    float l = g_as1[d * H1 + h] + ad;
    l = (l > 0.f) ? l : NEG * l;
    float den = __expf(l);
    float w = __shfl_sync(0xffffffffu, den, lane >> 2);
    float4 v = ((const float4*)(g_h1 + (size_t)d * HID))[lane];
    float4 acc; acc.x = v.x * w; acc.y = v.y * w; acc.z = v.z * w; acc.w = v.w * w;

    const int end = g_off[d + 1];
    int e = g_off[d];
    int s = (e < end) ? g_csr[e] : 0;
    for (; e < end; e++) {
        const int snext = (e + 1 < end) ? g_csr[e + 1] : 0;
        float ls = g_as1[s * H1 + h] + ad;
        ls = (ls > 0.f) ? ls : NEG * ls;
        const float ew = __expf(ls);
        den += ew;
        const float ww = __shfl_sync(0xffffffffu, ew, lane >> 2);
        const float4 u = ((const float4*)(g_h1 + (size_t)s * HID))[lane];
        acc.x += u.x * ww; acc.y += u.y * ww;
        acc.z += u.z * ww; acc.w += u.w * ww;
        s = snext;
    }

    const float dh  = __shfl_sync(0xffffffffu, den, lane >> 2);
    const float inv = __fdividef(1.f, dh);
    const float4 b = ((const float4*)bias1)[lane];
    const float4 r = ((const float4*)(g_res1 + (size_t)d * HID))[lane];
    float4 o;
    float t0;
    t0 = acc.x * inv + b.x; o.x = ((t0 > 0.f) ? t0 : (__expf(t0) - 1.f)) + r.x;
    t0 = acc.y * inv + b.y; o.y = ((t0 > 0.f) ? t0 : (__expf(t0) - 1.f)) + r.y;
    t0 = acc.z * inv + b.z; o.z = ((t0 > 0.f) ? t0 : (__expf(t0) - 1.f)) + r.z;
    t0 = acc.w * inv + b.w; o.w = ((t0 > 0.f) ? t0 : (__expf(t0) - 1.f)) + r.w;
    ((float4*)(g_h + (size_t)d * HID))[lane] = o;
}

// ---------------- Layer 2 node GEMM (f32x2): reads g_h -----------------------
__global__ void __launch_bounds__(160) k_gemm2(
        const float* __restrict__ W2,
        const float* __restrict__ res2W,
        const float* __restrict__ res2_b,
        const float* __restrict__ att_src2,
        const float* __restrict__ att_dst2)
{
    __shared__ __align__(16) float xs[128 * 36];   // [c][36]; reused as sred
    const int row0 = blockIdx.x * 32;
    const int t = threadIdx.x;

    for (int idx = t; idx < 32 * 128; idx += 160) {
        const int r = idx >> 7, c = idx & 127;
        xs[c * 36 + r] = g_h[(size_t)(row0 + r) * HID + c];
    }
    __syncthreads();

    const int col  = t % 80;            // 0..39 -> W2, 40..79 -> res2W
    const int half = t / 80;            // 0/1 -> rows [0,16) / [16,32)

    ull acc[8];
#pragma unroll
    for (int i = 0; i < 8; i++) acc[i] = 0ull;

    const float* Wc = (col < NCLS) ? (W2 + col) : (res2W + (col - NCLS));
#pragma unroll 2
    for (int k = 0; k < 128; k++) {
        const ull w = pack2(Wc[k * NCLS]);
        const ulonglong2* xp = (const ulonglong2*)(xs + k * 36 + half * 16);
#pragma unroll
        for (int i = 0; i < 4; i++) {
            const ulonglong2 xv = xp[i];
            fma2(acc[2 * i],     xv.x, w);
            fma2(acc[2 * i + 1], xv.y, w);
        }
    }
    __syncthreads();                    // xs reads done; alias sred
    float* sred = xs;                   // [2][32][NCLS]

    if (col < NCLS) {
        const float as = att_src2[col];
        const float ad = att_dst2[col];
#pragma unroll
        for (int i = 0; i < 8; i++) {
            const int lr = half * 16 + 2 * i;
            const int gr = row0 + lr;
            float lo, hi;
            unpack2(acc[i], lo, hi);
            g_h2[gr * NCLS + col]       = lo;
            g_h2[(gr + 1) * NCLS + col] = hi;
            sred[lr * NCLS + col]       = lo * as;
            sred[(lr + 1) * NCLS + col] = hi * as;
            sred[32 * NCLS + lr * NCLS + col]       = lo * ad;
            sred[32 * NCLS + (lr + 1) * NCLS + col] = hi * ad;
        }
    } else {
        const int jc = col - NCLS;
        const ull bp = pack2(res2_b[jc]);
#pragma unroll
        for (int i = 0; i < 8; i++) {
            const int gr = row0 + half * 16 + 2 * i;
            float lo, hi;
            unpack2(add2(acc[i], bp), lo, hi);
            g_res2[gr * NCLS + jc]       = lo;
            g_res2[(gr + 1) * NCLS + jc] = hi;
        }
    }
    __syncthreads();

    if (t < 32) {
        float ss = 0.f, dd = 0.f;
#pragma unroll 8
        for (int c = 0; c < NCLS; c++) {
            ss += sred[t * NCLS + c];
            dd += sred[32 * NCLS + t * NCLS + c];
        }
        g_as2[row0 + t] = ss;
        g_ad2[row0 + t] = dd;
    }
}

// ---------------- Layer 2 aggregation + log_softmax: warp per dst node -------
__global__ void k_edge2fin(const float* __restrict__ bias2,
                           float* __restrict__ out)
{
    const int d    = (blockIdx.x * blockDim.x + threadIdx.x) >> 5;
    const int lane = threadIdx.x & 31;
    if (d >= NNODES) return;

    const int grp = lane / 10;           // 0..2 active; 3 = lanes 30,31 (idle)
    const int sub = lane - grp * 10;
    const float ad = g_ad2[d];

    float den = 0.f;
    float4 acc; acc.x = acc.y = acc.z = acc.w = 0.f;

    if (grp == 0) {                      // self loop handled by group 0
        float l = g_as2[d] + ad;
        l = (l > 0.f) ? l : NEG * l;
        const float w = __expf(l);
        den = w;
        const float4 v = ((const float4*)(g_h2 + (size_t)d * NCLS))[sub];
        acc.x = v.x * w; acc.y = v.y * w; acc.z = v.z * w; acc.w = v.w * w;
    }

    if (grp < 3) {
        const int end = g_off[d + 1];
        for (int e = g_off[d] + grp; e < end; e += 3) {
            const int s = g_csr[e];
            float l = g_as2[s] + ad;
            l = (l > 0.f) ? l : NEG * l;
            const float w = __expf(l);
            den += w;
            const float4 v = ((const float4*)(g_h2 + (size_t)s * NCLS))[sub];
            acc.x += v.x * w; acc.y += v.y * w;
            acc.z += v.z * w; acc.w += v.w * w;
        }
    }

    const unsigned FULL = 0xffffffffu;
    float den_t = den + __shfl_sync(FULL, den, lane + 10)
                      + __shfl_sync(FULL, den, lane + 20);
    float ax = acc.x + __shfl_sync(FULL, acc.x, lane + 10) + __shfl_sync(FULL, acc.x, lane + 20);
    float ay = acc.y + __shfl_sync(FULL, acc.y, lane + 10) + __shfl_sync(FULL, acc.y, lane + 20);
    float az = acc.z + __shfl_sync(FULL, acc.z, lane + 10) + __shfl_sync(FULL, acc.z, lane + 20);
    float aw = acc.w + __shfl_sync(FULL, acc.w, lane + 10) + __shfl_sync(FULL, acc.w, lane + 20);

    const float inv = __fdividef(1.f, den_t);
    const float4 b = ((const float4*)bias2)[sub];
    const float4 r = ((const float4*)(g_res2 + (size_t)d * NCLS))[sub];
    float4 val;
    val.x = ax * inv + b.x + r.x;
    val.y = ay * inv + b.y + r.y;
    val.z = az * inv + b.z + r.z;
    val.w = aw * inv + b.w + r.w;

    float m = (lane < 10) ? fmaxf(fmaxf(val.x, val.y), fmaxf(val.z, val.w)) : -3.4e38f;
#pragma unroll
    for (int o = 16; o; o >>= 1) m = fmaxf(m, __shfl_xor_sync(FULL, m, o));
    float se = (lane < 10)
        ? (__expf(val.x - m) + __expf(val.y - m) + __expf(val.z - m) + __expf(val.w - m))
        : 0.f;
#pragma unroll
    for (int o = 16; o; o >>= 1) se += __shfl_xor_sync(FULL, se, o);
    const float lse = m + logf(se);

    if (lane < 10) {
        float4 o4;
        o4.x = val.x - lse; o4.y = val.y - lse;
        o4.z = val.z - lse; o4.w = val.w - lse;
        ((float4*)(out + (size_t)d * NCLS))[sub] = o4;
    }
}

// ---------------- launch ------------------------------------------------------
extern "C" void kernel_launch(void* const* d_in, const int* in_sizes, int n_in,
                              void* d_out, int out_size)
{
    const float* x   = (const float*)d_in[0];
    const int*   ei  = (const int*)d_in[1];
    const float* W1  = (const float*)d_in[2];
    const float* as1 = (const float*)d_in[3];
    const float* ad1 = (const float*)d_in[4];
    const float* b1  = (const float*)d_in[5];
    const float* W2  = (const float*)d_in[6];
    const float* as2 = (const float*)d_in[7];
    const float* ad2 = (const float*)d_in[8];
    const float* b2  = (const float*)d_in[9];
    const float* r1W = (const float*)d_in[10];
    const float* r1b = (const float*)d_in[11];
    const float* r2W = (const float*)d_in[12];
    const float* r2b = (const float*)d_in[13];

    const int E = in_sizes[1] / 2;

    k_detect <<<1, 32>>>(ei);
    k_zero   <<<(NNODES + 255) / 256, 256>>>();
    k_hist   <<<(E + 255) / 256, 256>>>(ei, E);
    k_scanA  <<<SCAN_BLKS, 1024>>>();
    k_scanB  <<<1, 128>>>();
    k_scanC  <<<SCAN_BLKS, 1024>>>();
    k_scatter<<<(E + 255) / 256, 256>>>(ei, E);
    k_gemm1  <<<NNODES / 32, 128>>>(x, W1, r1W, r1b, as1, ad1);
    k_edge1agg<<<(NNODES + 7) / 8, 256>>>(b1);
    k_gemm2  <<<NNODES / 32, 160>>>(W2, r2W, r2b, as2, ad2);
    k_edge2fin<<<(NNODES + 7) / 8, 256>>>(b2, (float*)d_out);
}

// round 8
// speedup vs baseline: 2.0542x; 1.0757x over previous
#include <cuda_runtime.h>

#define NNODES 100000
#define NFEAT  128
#define HID    128   // 8 heads * 16
#define H1     8
#define NCLS   40
#define NEG    0.2f
#define EMAX   1664000
#define SCAN_BLKS 98   // ceil(100000/1024)

typedef unsigned long long ull;

// ---------------- scratch (device globals; no runtime alloc) ----------------
__device__ __align__(16) float g_h1  [NNODES * HID];
__device__ __align__(16) float g_res1[NNODES * HID];
__device__ __align__(16) float g_as1 [NNODES * H1];
__device__ __align__(16) float g_ad1 [NNODES * H1];
__device__ __align__(16) float g_h   [NNODES * HID];
__device__ __align__(16) float g_h2  [NNODES * NCLS];
__device__ __align__(16) float g_res2[NNODES * NCLS];
__device__ __align__(16) float g_as2 [NNODES];
__device__ __align__(16) float g_ad2 [NNODES];
__device__ int g_deg[NNODES];
__device__ int g_off[NNODES + 1];
__device__ int g_cur[NNODES];
__device__ int g_csr[EMAX];
__device__ int g_bsum[128];
__device__ int g_is64;

// ---------------- f32x2 helpers ----------------------------------------------
__device__ __forceinline__ ull pack2(float v) {
    ull r; asm("mov.b64 %0, {%1,%1};" : "=l"(r) : "f"(v)); return r;
}
__device__ __forceinline__ void unpack2(ull v, float& lo, float& hi) {
    asm("mov.b64 {%0,%1}, %2;" : "=f"(lo), "=f"(hi) : "l"(v));
}
__device__ __forceinline__ void fma2(ull& acc, ull a, ull b) {
    asm("fma.rn.f32x2 %0, %1, %2, %0;" : "+l"(acc) : "l"(a), "l"(b));
}
__device__ __forceinline__ ull mul2(ull a, ull b) {
    ull c; asm("mul.rn.f32x2 %0, %1, %2;" : "=l"(c) : "l"(a), "l"(b)); return c;
}
__device__ __forceinline__ ull add2(ull a, ull b) {
    ull c; asm("add.rn.f32x2 %0, %1, %2;" : "=l"(c) : "l"(a), "l"(b)); return c;
}
__device__ __forceinline__ ull shfl_xor64(ull v, int o) {
    double d = __longlong_as_double((long long)v);
    d = __shfl_xor_sync(0xffffffffu, d, o);
    return (ull)__double_as_longlong(d);
}

// ---------------- edge_index dtype detection ---------------------------------
__global__ void k_detect(const int* __restrict__ ei32)
{
    if (threadIdx.x == 0 && blockIdx.x == 0) {
        long long s = 0;
        for (int i = 1; i < 128; i += 2) s += ei32[i];
        g_is64 = (s == 0) ? 1 : 0;
    }
}

__device__ __forceinline__ int edge_dst(const int* __restrict__ ei, int E, int e)
{
    return g_is64 ? (int)((const long long*)ei)[E + e] : ei[E + e];
}
__device__ __forceinline__ int edge_src(const int* __restrict__ ei, int E, int e)
{
    return g_is64 ? (int)((const long long*)ei)[e] : ei[e];
}

// ---------------- CSR build ----------------------------------------------------
__global__ void k_zero()
{
    const int i = blockIdx.x * blockDim.x + threadIdx.x;
    if (i < NNODES) { g_deg[i] = 0; g_cur[i] = 0; }
}

__global__ void k_hist(const int* __restrict__ ei, int E)
{
    const int e = blockIdx.x * blockDim.x + threadIdx.x;
    if (e >= E) return;
    atomicAdd(&g_deg[edge_dst(ei, E, e)], 1);
}

// phase A: per-block exclusive scan; block totals -> g_bsum
__global__ void __launch_bounds__(1024) k_scanA()
{
    __shared__ int wsum[32];
    const int t = threadIdx.x, lane = t & 31, wid = t >> 5;
    const int idx = blockIdx.x * 1024 + t;
    const int v = (idx < NNODES) ? g_deg[idx] : 0;

    int inc = v;
#pragma unroll
    for (int o = 1; o < 32; o <<= 1) {
        int n = __shfl_up_sync(0xffffffffu, inc, o);
        if (lane >= o) inc += n;
    }
    if (lane == 31) wsum[wid] = inc;
    __syncthreads();
    if (wid == 0) {
        int s = wsum[lane];
#pragma unroll
        for (int o = 1; o < 32; o <<= 1) {
            int n = __shfl_up_sync(0xffffffffu, s, o);
            if (lane >= o) s += n;
        }
        wsum[lane] = s;
    }
    __syncthreads();
    const int pre = (wid > 0) ? wsum[wid - 1] : 0;
    if (idx < NNODES) g_off[idx] = pre + inc - v;      // block-local exclusive
    if (t == 1023) g_bsum[blockIdx.x] = pre + inc;     // block total
}

// phase B: scan the block totals (1 block, 128 threads)
__global__ void k_scanB()
{
    __shared__ int sh[128];
    const int t = threadIdx.x;
    const int v = (t < SCAN_BLKS) ? g_bsum[t] : 0;
    sh[t] = v;
    __syncthreads();
#pragma unroll
    for (int o = 1; o < 128; o <<= 1) {
        const int n = (t >= o) ? sh[t - o] : 0;
        __syncthreads();
        sh[t] += n;
        __syncthreads();
    }
    g_bsum[t] = sh[t] - v;                  // exclusive
    if (t == 127) g_off[NNODES] = sh[127];  // grand total
}

// phase C: add block offsets
__global__ void __launch_bounds__(1024) k_scanC()
{
    const int idx = blockIdx.x * 1024 + threadIdx.x;
    if (idx < NNODES) g_off[idx] += g_bsum[blockIdx.x];
}

__global__ void k_scatter(const int* __restrict__ ei, int E)
{
    const int e = blockIdx.x * blockDim.x + threadIdx.x;
    if (e >= E) return;
    const int d = edge_dst(ei, E, e);
    const int s = edge_src(ei, E, e);
    const int pos = g_off[d] + atomicAdd(&g_cur[d], 1);
    g_csr[pos] = s;
}

// ---------------- Layer 1 node GEMM (f32x2): 32 rows x 256 cols per block ----
__global__ void __launch_bounds__(128) k_gemm1(
        const float* __restrict__ x,
        const float* __restrict__ W1,
        const float* __restrict__ resW,
        const float* __restrict__ res_b,
        const float* __restrict__ att_src,
        const float* __restrict__ att_dst)
{
    __shared__ __align__(16) float xs[128 * 36];  // [k][36]
    const int row0 = blockIdx.x * 32;
    const int t = threadIdx.x;

#pragma unroll 4
    for (int r = 0; r < 32; r++)
        xs[t * 36 + r] = x[(row0 + r) * NFEAT + t];
    __syncthreads();

    ull accA[16], accB[16];
#pragma unroll
    for (int i = 0; i < 16; i++) { accA[i] = 0ull; accB[i] = 0ull; }

    const float* WA = W1 + t;     // stride 128
    const float* WB = resW + t;   // stride 128

#pragma unroll 2
    for (int k = 0; k < 128; k++) {
        const ull wa = pack2(WA[k * 128]);
        const ull wb = pack2(WB[k * 128]);
        const ulonglong2* xp = (const ulonglong2*)(xs + k * 36);
#pragma unroll
        for (int i = 0; i < 8; i++) {
            const ulonglong2 xv = xp[i];
            fma2(accA[2 * i],     xv.x, wa);
            fma2(accA[2 * i + 1], xv.y, wa);
            fma2(accB[2 * i],     xv.x, wb);
            fma2(accB[2 * i + 1], xv.y, wb);
        }
    }

    const ull asp = pack2(att_src[t]);   // (8,16) row-major: head=t>>4
    const ull adp = pack2(att_dst[t]);
    const ull bbp = pack2(res_b[t]);
    const int head = t >> 4;

#pragma unroll
    for (int i = 0; i < 16; i++) {
        const int gr = row0 + 2 * i;
        float lo, hi;
        unpack2(accA[i], lo, hi);
        g_h1[gr * HID + t]       = lo;
        g_h1[(gr + 1) * HID + t] = hi;

        ull vs = mul2(accA[i], asp);
        ull vd = mul2(accA[i], adp);
#pragma unroll
        for (int o = 8; o; o >>= 1) {
            vs = add2(vs, shfl_xor64(vs, o));
            vd = add2(vd, shfl_xor64(vd, o));
        }
        if ((t & 15) == 0) {
            float s0, s1, d0, d1;
            unpack2(vs, s0, s1); unpack2(vd, d0, d1);
            g_as1[gr * H1 + head]       = s0;
            g_as1[(gr + 1) * H1 + head] = s1;
            g_ad1[gr * H1 + head]       = d0;
            g_ad1[(gr + 1) * H1 + head] = d1;
        }

        ull rb = add2(accB[i], bbp);
        unpack2(rb, lo, hi);
        g_res1[gr * HID + t]       = lo;
        g_res1[(gr + 1) * HID + t] = hi;
    }
}

// ---------------- Layer 1 aggregation: warp per dst node, CSR gather ---------
// 2 edges/iteration for MLP; register accumulation; fused finalize -> g_h.
__global__ void k_edge1agg(const float* __restrict__ bias1)
{
    const int d    = (blockIdx.x * blockDim.x + threadIdx.x) >> 5;
    const int lane = threadIdx.x & 31;
    if (d >= NNODES) return;

    const int h = lane & 7;
    const float ad = g_ad1[d * H1 + h];

    // self loop
    float l = g_as1[d * H1 + h] + ad;
    l = (l > 0.f) ? l : NEG * l;
    float den = __expf(l);
    float w = __shfl_sync(0xffffffffu, den, lane >> 2);
    float4 v = ((const float4*)(g_h1 + (size_t)d * HID))[lane];
    float4 acc; acc.x = v.x * w; acc.y = v.y * w; acc.z = v.z * w; acc.w = v.w * w;

    const int end = g_off[d + 1];
    int e = g_off[d];
    for (; e + 2 <= end; e += 2) {
        const int s0 = g_csr[e];
        const int s1 = g_csr[e + 1];
        float l0 = g_as1[s0 * H1 + h] + ad;
        float l1 = g_as1[s1 * H1 + h] + ad;
        l0 = (l0 > 0.f) ? l0 : NEG * l0;
        l1 = (l1 > 0.f) ? l1 : NEG * l1;
        const float e0 = __expf(l0);
        const float e1 = __expf(l1);
        den += e0 + e1;
        const float w0 = __shfl_sync(0xffffffffu, e0, lane >> 2);
        const float w1 = __shfl_sync(0xffffffffu, e1, lane >> 2);
        const float4 u0 = ((const float4*)(g_h1 + (size_t)s0 * HID))[lane];
        const float4 u1 = ((const float4*)(g_h1 + (size_t)s1 * HID))[lane];
        acc.x += u0.x * w0; acc.y += u0.y * w0;
        acc.z += u0.z * w0; acc.w += u0.w * w0;
        acc.x += u1.x * w1; acc.y += u1.y * w1;
        acc.z += u1.z * w1; acc.w += u1.w * w1;
    }
    if (e < end) {
        const int s = g_csr[e];
        float ls = g_as1[s * H1 + h] + ad;
        ls = (ls > 0.f) ? ls : NEG * ls;
        const float ew = __expf(ls);
        den += ew;
        const float ww = __shfl_sync(0xffffffffu, ew, lane >> 2);
        const float4 u = ((const float4*)(g_h1 + (size_t)s * HID))[lane];
        acc.x += u.x * ww; acc.y += u.y * ww;
        acc.z += u.z * ww; acc.w += u.w * ww;
    }

    const float dh  = __shfl_sync(0xffffffffu, den, lane >> 2);
    const float inv = __fdividef(1.f, dh);
    const float4 b = ((const float4*)bias1)[lane];
    const float4 r = ((const float4*)(g_res1 + (size_t)d * HID))[lane];
    float4 o;
    float t0;
    t0 = acc.x * inv + b.x; o.x = ((t0 > 0.f) ? t0 : (__expf(t0) - 1.f)) + r.x;
    t0 = acc.y * inv + b.y; o.y = ((t0 > 0.f) ? t0 : (__expf(t0) - 1.f)) + r.y;
    t0 = acc.z * inv + b.z; o.z = ((t0 > 0.f) ? t0 : (__expf(t0) - 1.f)) + r.z;
    t0 = acc.w * inv + b.w; o.w = ((t0 > 0.f) ? t0 : (__expf(t0) - 1.f)) + r.w;
    ((float4*)(g_h + (size_t)d * HID))[lane] = o;
}

// ---------------- Layer 2 node GEMM (f32x2): reads g_h -----------------------
__global__ void __launch_bounds__(160) k_gemm2(
        const float* __restrict__ W2,
        const float* __restrict__ res2W,
        const float* __restrict__ res2_b,
        const float* __restrict__ att_src2,
        const float* __restrict__ att_dst2)
{
    __shared__ __align__(16) float xs[128 * 36];   // [c][36]; reused as sred
    const int row0 = blockIdx.x * 32;
    const int t = threadIdx.x;

    for (int idx = t; idx < 32 * 128; idx += 160) {
        const int r = idx >> 7, c = idx & 127;
        xs[c * 36 + r] = g_h[(size_t)(row0 + r) * HID + c];
    }
    __syncthreads();

    const int col  = t % 80;            // 0..39 -> W2, 40..79 -> res2W
    const int half = t / 80;            // 0/1 -> rows [0,16) / [16,32)

    ull acc[8];
#pragma unroll
    for (int i = 0; i < 8; i++) acc[i] = 0ull;

    const float* Wc = (col < NCLS) ? (W2 + col) : (res2W + (col - NCLS));
#pragma unroll 2
    for (int k = 0; k < 128; k++) {
        const ull w = pack2(Wc[k * NCLS]);
        const ulonglong2* xp = (const ulonglong2*)(xs + k * 36 + half * 16);
#pragma unroll
        for (int i = 0; i < 4; i++) {
            const ulonglong2 xv = xp[i];
            fma2(acc[2 * i],     xv.x, w);
            fma2(acc[2 * i + 1], xv.y, w);
        }
    }
    __syncthreads();                    // xs reads done; alias sred
    float* sred = xs;                   // [2][32][NCLS]

    if (col < NCLS) {
        const float as = att_src2[col];
        const float ad = att_dst2[col];
#pragma unroll
        for (int i = 0; i < 8; i++) {
            const int lr = half * 16 + 2 * i;
            const int gr = row0 + lr;
            float lo, hi;
            unpack2(acc[i], lo, hi);
            g_h2[gr * NCLS + col]       = lo;
            g_h2[(gr + 1) * NCLS + col] = hi;
            sred[lr * NCLS + col]       = lo * as;
            sred[(lr + 1) * NCLS + col] = hi * as;
            sred[32 * NCLS + lr * NCLS + col]       = lo * ad;
            sred[32 * NCLS + (lr + 1) * NCLS + col] = hi * ad;
        }
    } else {
        const int jc = col - NCLS;
        const ull bp = pack2(res2_b[jc]);
#pragma unroll
        for (int i = 0; i < 8; i++) {
            const int gr = row0 + half * 16 + 2 * i;
            float lo, hi;
            unpack2(add2(acc[i], bp), lo, hi);
            g_res2[gr * NCLS + jc]       = lo;
            g_res2[(gr + 1) * NCLS + jc] = hi;
        }
    }
    __syncthreads();

    if (t < 32) {
        float ss = 0.f, dd = 0.f;
#pragma unroll 8
        for (int c = 0; c < NCLS; c++) {
            ss += sred[t * NCLS + c];
            dd += sred[32 * NCLS + t * NCLS + c];
        }
        g_as2[row0 + t] = ss;
        g_ad2[row0 + t] = dd;
    }
}

// ---------------- Layer 2 aggregation + log_softmax: warp per dst node -------
__global__ void k_edge2fin(const float* __restrict__ bias2,
                           float* __restrict__ out)
{
    const int d    = (blockIdx.x * blockDim.x + threadIdx.x) >> 5;
    const int lane = threadIdx.x & 31;
    if (d >= NNODES) return;

    const int grp = lane / 10;           // 0..2 active; 3 = lanes 30,31 (idle)
    const int sub = lane - grp * 10;
    const float ad = g_ad2[d];

    float den = 0.f;
    float4 acc; acc.x = acc.y = acc.z = acc.w = 0.f;

    if (grp == 0) {                      // self loop handled by group 0
        float l = g_as2[d] + ad;
        l = (l > 0.f) ? l : NEG * l;
        const float w = __expf(l);
        den = w;
        const float4 v = ((const float4*)(g_h2 + (size_t)d * NCLS))[sub];
        acc.x = v.x * w; acc.y = v.y * w; acc.z = v.z * w; acc.w = v.w * w;
    }

    if (grp < 3) {
        const int end = g_off[d + 1];
        for (int e = g_off[d] + grp; e < end; e += 3) {
            const int s = g_csr[e];
            float l = g_as2[s] + ad;
            l = (l > 0.f) ? l : NEG * l;
            const float w = __expf(l);
            den += w;
            const float4 v = ((const float4*)(g_h2 + (size_t)s * NCLS))[sub];
            acc.x += v.x * w; acc.y += v.y * w;
            acc.z += v.z * w; acc.w += v.w * w;
        }
    }

    const unsigned FULL = 0xffffffffu;
    float den_t = den + __shfl_sync(FULL, den, lane + 10)
                      + __shfl_sync(FULL, den, lane + 20);
    float ax = acc.x + __shfl_sync(FULL, acc.x, lane + 10) + __shfl_sync(FULL, acc.x, lane + 20);
    float ay = acc.y + __shfl_sync(FULL, acc.y, lane + 10) + __shfl_sync(FULL, acc.y, lane + 20);
    float az = acc.z + __shfl_sync(FULL, acc.z, lane + 10) + __shfl_sync(FULL, acc.z, lane + 20);
    float aw = acc.w + __shfl_sync(FULL, acc.w, lane + 10) + __shfl_sync(FULL, acc.w, lane + 20);

    const float inv = __fdividef(1.f, den_t);
    const float4 b = ((const float4*)bias2)[sub];
    const float4 r = ((const float4*)(g_res2 + (size_t)d * NCLS))[sub];
    float4 val;
    val.x = ax * inv + b.x + r.x;
    val.y = ay * inv + b.y + r.y;
    val.z = az * inv + b.z + r.z;
    val.w = aw * inv + b.w + r.w;

    float m = (lane < 10) ? fmaxf(fmaxf(val.x, val.y), fmaxf(val.z, val.w)) : -3.4e38f;
#pragma unroll
    for (int o = 16; o; o >>= 1) m = fmaxf(m, __shfl_xor_sync(FULL, m, o));
    float se = (lane < 10)
        ? (__expf(val.x - m) + __expf(val.y - m) + __expf(val.z - m) + __expf(val.w - m))
        : 0.f;
#pragma unroll
    for (int o = 16; o; o >>= 1) se += __shfl_xor_sync(FULL, se, o);
    const float lse = m + logf(se);

    if (lane < 10) {
        float4 o4;
        o4.x = val.x - lse; o4.y = val.y - lse;
        o4.z = val.z - lse; o4.w = val.w - lse;
        ((float4*)(out + (size_t)d * NCLS))[sub] = o4;
    }
}

// ---------------- launch ------------------------------------------------------
extern "C" void kernel_launch(void* const* d_in, const int* in_sizes, int n_in,
                              void* d_out, int out_size)
{
    const float* x   = (const float*)d_in[0];
    const int*   ei  = (const int*)d_in[1];
    const float* W1  = (const float*)d_in[2];
    const float* as1 = (const float*)d_in[3];
    const float* ad1 = (const float*)d_in[4];
    const float* b1  = (const float*)d_in[5];
    const float* W2  = (const float*)d_in[6];
    const float* as2 = (const float*)d_in[7];
    const float* ad2 = (const float*)d_in[8];
    const float* b2  = (const float*)d_in[9];
    const float* r1W = (const float*)d_in[10];
    const float* r1b = (const float*)d_in[11];
    const float* r2W = (const float*)d_in[12];
    const float* r2b = (const float*)d_in[13];

    const int E = in_sizes[1] / 2;

    // lazy one-time creation (first call is the non-captured correctness run;
    // identical launch sequence on every call — no work is skipped)
    static cudaStream_t s_csr = nullptr;
    static cudaEvent_t ev_fork = nullptr, ev_join = nullptr;
    if (s_csr == nullptr) {
        cudaStreamCreate(&s_csr);
        cudaEventCreateWithFlags(&ev_fork, cudaEventDisableTiming);
        cudaEventCreateWithFlags(&ev_join, cudaEventDisableTiming);
    }

    // main stream: detect (needed by CSR branch), then fork
    k_detect<<<1, 32>>>(ei);
    cudaEventRecord(ev_fork, 0);
    cudaStreamWaitEvent(s_csr, ev_fork, 0);

    // CSR branch (independent of gemm1)
    k_zero   <<<(NNODES + 255) / 256, 256, 0, s_csr>>>();
    k_hist   <<<(E + 255) / 256, 256, 0, s_csr>>>(ei, E);
    k_scanA  <<<SCAN_BLKS, 1024, 0, s_csr>>>();
    k_scanB  <<<1, 128, 0, s_csr>>>();
    k_scanC  <<<SCAN_BLKS, 1024, 0, s_csr>>>();
    k_scatter<<<(E + 255) / 256, 256, 0, s_csr>>>(ei, E);
    cudaEventRecord(ev_join, s_csr);

    // main stream: gemm1 runs concurrently with CSR build
    k_gemm1  <<<NNODES / 32, 128>>>(x, W1, r1W, r1b, as1, ad1);

    // join: edge1agg needs both gemm1 and the CSR
    cudaStreamWaitEvent(0, ev_join, 0);
    k_edge1agg<<<(NNODES + 7) / 8, 256>>>(b1);
    k_gemm2  <<<NNODES / 32, 160>>>(W2, r2W, r2b, as2, ad2);
    k_edge2fin<<<(NNODES + 7) / 8, 256>>>(b2, (float*)d_out);
}

// round 9
// speedup vs baseline: 2.3720x; 1.1547x over previous
#include <cuda_runtime.h>

#define NNODES 100000
#define NFEAT  128
#define HID    128   // 8 heads * 16
#define H1     8
#define NCLS   40
#define NEG    0.2f
#define EMAX   1664000
#define SCAN_BLKS 98   // ceil(100000/1024)

typedef unsigned long long ull;

// ---------------- scratch (device globals; no runtime alloc) ----------------
__device__ __align__(16) float g_h1  [NNODES * HID];
__device__ __align__(16) float g_res1[NNODES * HID];
__device__ __align__(16) float g_as1 [NNODES * H1];
__device__ __align__(16) float g_ad1 [NNODES * H1];
__device__ __align__(16) float g_h   [NNODES * HID];
__device__ __align__(16) float g_h2  [NNODES * NCLS];
__device__ __align__(16) float g_res2[NNODES * NCLS];
__device__ __align__(16) float g_as2 [NNODES];
__device__ __align__(16) float g_ad2 [NNODES];
__device__ int g_deg[NNODES];
__device__ int g_off[NNODES + 1];
__device__ int g_cur[NNODES];
__device__ int g_csr[EMAX];
__device__ int g_bsum[128];
__device__ int g_is64;

// ---------------- f32x2 helpers ----------------------------------------------
__device__ __forceinline__ ull pack2(float v) {
    ull r; asm("mov.b64 %0, {%1,%1};" : "=l"(r) : "f"(v)); return r;
}
__device__ __forceinline__ void unpack2(ull v, float& lo, float& hi) {
    asm("mov.b64 {%0,%1}, %2;" : "=f"(lo), "=f"(hi) : "l"(v));
}
__device__ __forceinline__ void fma2(ull& acc, ull a, ull b) {
    asm("fma.rn.f32x2 %0, %1, %2, %0;" : "+l"(acc) : "l"(a), "l"(b));
}
__device__ __forceinline__ ull mul2(ull a, ull b) {
    ull c; asm("mul.rn.f32x2 %0, %1, %2;" : "=l"(c) : "l"(a), "l"(b)); return c;
}
__device__ __forceinline__ ull add2(ull a, ull b) {
    ull c; asm("add.rn.f32x2 %0, %1, %2;" : "=l"(c) : "l"(a), "l"(b)); return c;
}
__device__ __forceinline__ ull shfl_xor64(ull v, int o) {
    double d = __longlong_as_double((long long)v);
    d = __shfl_xor_sync(0xffffffffu, d, o);
    return (ull)__double_as_longlong(d);
}

// ---------------- edge_index dtype detection (warp-parallel) ------------------
__global__ void k_detect(const int* __restrict__ ei32)
{
    const int lane = threadIdx.x & 31;
    long long s = (long long)ei32[2 * lane + 1] + (long long)ei32[2 * lane + 65];
#pragma unroll
    for (int o = 16; o; o >>= 1)
        s += __shfl_xor_sync(0xffffffffu, s, o);
    if (lane == 0) g_is64 = (s == 0) ? 1 : 0;
}

__device__ __forceinline__ int edge_dst(const int* __restrict__ ei, int E, int e)
{
    return g_is64 ? (int)((const long long*)ei)[E + e] : ei[E + e];
}
__device__ __forceinline__ int edge_src(const int* __restrict__ ei, int E, int e)
{
    return g_is64 ? (int)((const long long*)ei)[e] : ei[e];
}

// ---------------- CSR build ----------------------------------------------------
__global__ void k_zero()
{
    const int i = blockIdx.x * blockDim.x + threadIdx.x;
    if (i < NNODES) { g_deg[i] = 0; g_cur[i] = 0; }
}

__global__ void k_hist(const int* __restrict__ ei, int E)
{
    const int e = blockIdx.x * blockDim.x + threadIdx.x;
    if (e >= E) return;
    atomicAdd(&g_deg[edge_dst(ei, E, e)], 1);
}

// phase A: per-block exclusive scan; block totals -> g_bsum
__global__ void __launch_bounds__(1024) k_scanA()
{
    __shared__ int wsum[32];
    const int t = threadIdx.x, lane = t & 31, wid = t >> 5;
    const int idx = blockIdx.x * 1024 + t;
    const int v = (idx < NNODES) ? g_deg[idx] : 0;

    int inc = v;
#pragma unroll
    for (int o = 1; o < 32; o <<= 1) {
        int n = __shfl_up_sync(0xffffffffu, inc, o);
        if (lane >= o) inc += n;
    }
    if (lane == 31) wsum[wid] = inc;
    __syncthreads();
    if (wid == 0) {
        int s = wsum[lane];
#pragma unroll
        for (int o = 1; o < 32; o <<= 1) {
            int n = __shfl_up_sync(0xffffffffu, s, o);
            if (lane >= o) s += n;
        }
        wsum[lane] = s;
    }
    __syncthreads();
    const int pre = (wid > 0) ? wsum[wid - 1] : 0;
    if (idx < NNODES) g_off[idx] = pre + inc - v;      // block-local exclusive
    if (t == 1023) g_bsum[blockIdx.x] = pre + inc;     // block total
}

// phase B: scan the block totals (1 block, 128 threads)
__global__ void k_scanB()
{
    __shared__ int sh[128];
    const int t = threadIdx.x;
    const int v = (t < SCAN_BLKS) ? g_bsum[t] : 0;
    sh[t] = v;
    __syncthreads();
#pragma unroll
    for (int o = 1; o < 128; o <<= 1) {
        const int n = (t >= o) ? sh[t - o] : 0;
        __syncthreads();
        sh[t] += n;
        __syncthreads();
    }
    g_bsum[t] = sh[t] - v;                  // exclusive
    if (t == 127) g_off[NNODES] = sh[127];  // grand total
}

// phase C: add block offsets
__global__ void __launch_bounds__(1024) k_scanC()
{
    const int idx = blockIdx.x * 1024 + threadIdx.x;
    if (idx < NNODES) g_off[idx] += g_bsum[blockIdx.x];
}

__global__ void k_scatter(const int* __restrict__ ei, int E)
{
    const int e = blockIdx.x * blockDim.x + threadIdx.x;
    if (e >= E) return;
    const int d = edge_dst(ei, E, e);
    const int s = edge_src(ei, E, e);
    const int pos = g_off[d] + atomicAdd(&g_cur[d], 1);
    g_csr[pos] = s;
}

// ---------------- Layer 1 node GEMM (f32x2): 32 rows x 256 cols per block ----
__global__ void __launch_bounds__(128) k_gemm1(
        const float* __restrict__ x,
        const float* __restrict__ W1,
        const float* __restrict__ resW,
        const float* __restrict__ res_b,
        const float* __restrict__ att_src,
        const float* __restrict__ att_dst)
{
    __shared__ __align__(16) float xs[128 * 36];  // [k][36]
    const int row0 = blockIdx.x * 32;
    const int t = threadIdx.x;

#pragma unroll 4
    for (int r = 0; r < 32; r++)
        xs[t * 36 + r] = x[(row0 + r) * NFEAT + t];
    __syncthreads();

    ull accA[16], accB[16];
#pragma unroll
    for (int i = 0; i < 16; i++) { accA[i] = 0ull; accB[i] = 0ull; }

    const float* WA = W1 + t;     // stride 128
    const float* WB = resW + t;   // stride 128

#pragma unroll 4
    for (int k = 0; k < 128; k++) {
        const ull wa = pack2(WA[k * 128]);
        const ull wb = pack2(WB[k * 128]);
        const ulonglong2* xp = (const ulonglong2*)(xs + k * 36);
#pragma unroll
        for (int i = 0; i < 8; i++) {
            const ulonglong2 xv = xp[i];
            fma2(accA[2 * i],     xv.x, wa);
            fma2(accA[2 * i + 1], xv.y, wa);
            fma2(accB[2 * i],     xv.x, wb);
            fma2(accB[2 * i + 1], xv.y, wb);
        }
    }

    const ull asp = pack2(att_src[t]);   // (8,16) row-major: head=t>>4
    const ull adp = pack2(att_dst[t]);
    const ull bbp = pack2(res_b[t]);
    const int head = t >> 4;

#pragma unroll
    for (int i = 0; i < 16; i++) {
        const int gr = row0 + 2 * i;
        float lo, hi;
        unpack2(accA[i], lo, hi);
        g_h1[gr * HID + t]       = lo;
        g_h1[(gr + 1) * HID + t] = hi;

        ull vs = mul2(accA[i], asp);
        ull vd = mul2(accA[i], adp);
#pragma unroll
        for (int o = 8; o; o >>= 1) {
            vs = add2(vs, shfl_xor64(vs, o));
            vd = add2(vd, shfl_xor64(vd, o));
        }
        if ((t & 15) == 0) {
            float s0, s1, d0, d1;
            unpack2(vs, s0, s1); unpack2(vd, d0, d1);
            g_as1[gr * H1 + head]       = s0;
            g_as1[(gr + 1) * H1 + head] = s1;
            g_ad1[gr * H1 + head]       = d0;
            g_ad1[(gr + 1) * H1 + head] = d1;
        }

        ull rb = add2(accB[i], bbp);
        unpack2(rb, lo, hi);
        g_res1[gr * HID + t]       = lo;
        g_res1[(gr + 1) * HID + t] = hi;
    }
}

// ---------------- Layer 1 aggregation: warp per dst node, CSR gather ---------
__global__ void k_edge1agg(const float* __restrict__ bias1)
{
    const int d    = (blockIdx.x * blockDim.x + threadIdx.x) >> 5;
    const int lane = threadIdx.x & 31;
    if (d >= NNODES) return;

    const int h = lane & 7;
    const float ad = g_ad1[d * H1 + h];

    // self loop
    float l = g_as1[d * H1 + h] + ad;
    l = (l > 0.f) ? l : NEG * l;
    float den = __expf(l);
    float w = __shfl_sync(0xffffffffu, den, lane >> 2);
    float4 v = ((const float4*)(g_h1 + (size_t)d * HID))[lane];
    float4 acc; acc.x = v.x * w; acc.y = v.y * w; acc.z = v.z * w; acc.w = v.w * w;

    const int end = g_off[d + 1];
    int e = g_off[d];
    for (; e + 2 <= end; e += 2) {
        const int s0 = g_csr[e];
        const int s1 = g_csr[e + 1];
        float l0 = g_as1[s0 * H1 + h] + ad;
        float l1 = g_as1[s1 * H1 + h] + ad;
        l0 = (l0 > 0.f) ? l0 : NEG * l0;
        l1 = (l1 > 0.f) ? l1 : NEG * l1;
        const float e0 = __expf(l0);
        const float e1 = __expf(l1);
        den += e0 + e1;
        const float w0 = __shfl_sync(0xffffffffu, e0, lane >> 2);
        const float w1 = __shfl_sync(0xffffffffu, e1, lane >> 2);
        const float4 u0 = ((const float4*)(g_h1 + (size_t)s0 * HID))[lane];
        const float4 u1 = ((const float4*)(g_h1 + (size_t)s1 * HID))[lane];
        acc.x += u0.x * w0; acc.y += u0.y * w0;
        acc.z += u0.z * w0; acc.w += u0.w * w0;
        acc.x += u1.x * w1; acc.y += u1.y * w1;
        acc.z += u1.z * w1; acc.w += u1.w * w1;
    }
    if (e < end) {
        const int s = g_csr[e];
        float ls = g_as1[s * H1 + h] + ad;
        ls = (ls > 0.f) ? ls : NEG * ls;
        const float ew = __expf(ls);
        den += ew;
        const float ww = __shfl_sync(0xffffffffu, ew, lane >> 2);
        const float4 u = ((const float4*)(g_h1 + (size_t)s * HID))[lane];
        acc.x += u.x * ww; acc.y += u.y * ww;
        acc.z += u.z * ww; acc.w += u.w * ww;
    }

    const float dh  = __shfl_sync(0xffffffffu, den, lane >> 2);
    const float inv = __fdividef(1.f, dh);
    const float4 b = ((const float4*)bias1)[lane];
    const float4 r = ((const float4*)(g_res1 + (size_t)d * HID))[lane];
    float4 o;
    float t0;
    t0 = acc.x * inv + b.x; o.x = ((t0 > 0.f) ? t0 : (__expf(t0) - 1.f)) + r.x;
    t0 = acc.y * inv + b.y; o.y = ((t0 > 0.f) ? t0 : (__expf(t0) - 1.f)) + r.y;
    t0 = acc.z * inv + b.z; o.z = ((t0 > 0.f) ? t0 : (__expf(t0) - 1.f)) + r.z;
    t0 = acc.w * inv + b.w; o.w = ((t0 > 0.f) ? t0 : (__expf(t0) - 1.f)) + r.w;
    ((float4*)(g_h + (size_t)d * HID))[lane] = o;
}

// ---------------- Layer 2 node GEMM (f32x2): 64-row tiles, dual-col threads --
// 160 threads = 40 dual-col threads (W2 col + res2W col) x 4 row-groups of 16.
__global__ void __launch_bounds__(160) k_gemm2(
        const float* __restrict__ W2,
        const float* __restrict__ res2W,
        const float* __restrict__ res2_b,
        const float* __restrict__ att_src2,
        const float* __restrict__ att_dst2)
{
    __shared__ __align__(16) float xs[128 * 68];   // [c][68]; reused as sred
    const int row0 = blockIdx.x * 64;
    const int t = threadIdx.x;

    for (int idx = t; idx < 64 * 128; idx += 160) {
        const int r = idx >> 7, c = idx & 127;
        const int row = row0 + r;
        xs[c * 68 + r] = (row < NNODES) ? g_h[(size_t)row * HID + c] : 0.f;
    }
    __syncthreads();

    const int col = t % 40;
    const int grp = t / 40;             // 0..3 -> rows [16*grp, 16*grp+16)

    ull accA[8], accB[8];
#pragma unroll
    for (int i = 0; i < 8; i++) { accA[i] = 0ull; accB[i] = 0ull; }

    const float* WA = W2 + col;         // stride 40
    const float* WB = res2W + col;      // stride 40
#pragma unroll 4
    for (int k = 0; k < 128; k++) {
        const ull wa = pack2(WA[k * NCLS]);
        const ull wb = pack2(WB[k * NCLS]);
        const ulonglong2* xp = (const ulonglong2*)(xs + k * 68 + grp * 16);
#pragma unroll
        for (int i = 0; i < 4; i++) {
            const ulonglong2 xv = xp[i];
            fma2(accA[2 * i],     xv.x, wa);
            fma2(accA[2 * i + 1], xv.y, wa);
            fma2(accB[2 * i],     xv.x, wb);
            fma2(accB[2 * i + 1], xv.y, wb);
        }
    }
    __syncthreads();                    // xs reads done; alias sred
    float* sred = xs;                   // [2][64][NCLS] = 20480B

    const float as = att_src2[col];
    const float adw = att_dst2[col];
    const ull bp = pack2(res2_b[col]);
#pragma unroll
    for (int i = 0; i < 8; i++) {
        const int lr = grp * 16 + 2 * i;
        const int gr = row0 + lr;
        float lo, hi;
        unpack2(accA[i], lo, hi);
        sred[lr * NCLS + col]       = lo * as;
        sred[(lr + 1) * NCLS + col] = hi * as;
        sred[64 * NCLS + lr * NCLS + col]       = lo * adw;
        sred[64 * NCLS + (lr + 1) * NCLS + col] = hi * adw;
        float rlo, rhi;
        unpack2(add2(accB[i], bp), rlo, rhi);
        if (gr < NNODES) {
            g_h2  [gr * NCLS + col] = lo;
            g_res2[gr * NCLS + col] = rlo;
        }
        if (gr + 1 < NNODES) {
            g_h2  [(gr + 1) * NCLS + col] = hi;
            g_res2[(gr + 1) * NCLS + col] = rhi;
        }
    }
    __syncthreads();

    if (t < 64 && row0 + t < NNODES) {
        float ss = 0.f, dd = 0.f;
#pragma unroll 8
        for (int c = 0; c < NCLS; c++) {
            ss += sred[t * NCLS + c];
            dd += sred[64 * NCLS + t * NCLS + c];
        }
        g_as2[row0 + t] = ss;
        g_ad2[row0 + t] = dd;
    }
}

// ---------------- Layer 2 aggregation + log_softmax: warp per dst node -------
__global__ void k_edge2fin(const float* __restrict__ bias2,
                           float* __restrict__ out)
{
    const int d    = (blockIdx.x * blockDim.x + threadIdx.x) >> 5;
    const int lane = threadIdx.x & 31;
    if (d >= NNODES) return;

    const int grp = lane / 10;           // 0..2 active; 3 = lanes 30,31 (idle)
    const int sub = lane - grp * 10;
    const float ad = g_ad2[d];

    float den = 0.f;
    float4 acc; acc.x = acc.y = acc.z = acc.w = 0.f;

    if (grp == 0) {                      // self loop handled by group 0
        float l = g_as2[d] + ad;
        l = (l > 0.f) ? l : NEG * l;
        const float w = __expf(l);
        den = w;
        const float4 v = ((const float4*)(g_h2 + (size_t)d * NCLS))[sub];
        acc.x = v.x * w; acc.y = v.y * w; acc.z = v.z * w; acc.w = v.w * w;
    }

    if (grp < 3) {
        const int end = g_off[d + 1];
        int e = g_off[d] + grp;
        for (; e + 3 < end; e += 6) {    // 2 edges in flight per group
            const int s0 = g_csr[e];
            const int s1 = g_csr[e + 3];
            float l0 = g_as2[s0] + ad;
            float l1 = g_as2[s1] + ad;
            l0 = (l0 > 0.f) ? l0 : NEG * l0;
            l1 = (l1 > 0.f) ? l1 : NEG * l1;
            const float w0 = __expf(l0);
            const float w1 = __expf(l1);
            den += w0 + w1;
            const float4 v0 = ((const float4*)(g_h2 + (size_t)s0 * NCLS))[sub];
            const float4 v1 = ((const float4*)(g_h2 + (size_t)s1 * NCLS))[sub];
            acc.x += v0.x * w0; acc.y += v0.y * w0;
            acc.z += v0.z * w0; acc.w += v0.w * w0;
            acc.x += v1.x * w1; acc.y += v1.y * w1;
            acc.z += v1.z * w1; acc.w += v1.w * w1;
        }
        if (e < end) {
            const int s = g_csr[e];
            float l = g_as2[s] + ad;
            l = (l > 0.f) ? l : NEG * l;
            const float w = __expf(l);
            den += w;
            const float4 v = ((const float4*)(g_h2 + (size_t)s * NCLS))[sub];
            acc.x += v.x * w; acc.y += v.y * w;
            acc.z += v.z * w; acc.w += v.w * w;
        }
    }

    const unsigned FULL = 0xffffffffu;
    float den_t = den + __shfl_sync(FULL, den, lane + 10)
                      + __shfl_sync(FULL, den, lane + 20);
    float ax = acc.x + __shfl_sync(FULL, acc.x, lane + 10) + __shfl_sync(FULL, acc.x, lane + 20);
    float ay = acc.y + __shfl_sync(FULL, acc.y, lane + 10) + __shfl_sync(FULL, acc.y, lane + 20);
    float az = acc.z + __shfl_sync(FULL, acc.z, lane + 10) + __shfl_sync(FULL, acc.z, lane + 20);
    float aw = acc.w + __shfl_sync(FULL, acc.w, lane + 10) + __shfl_sync(FULL, acc.w, lane + 20);

    const float inv = __fdividef(1.f, den_t);
    const float4 b = ((const float4*)bias2)[sub];
    const float4 r = ((const float4*)(g_res2 + (size_t)d * NCLS))[sub];
    float4 val;
    val.x = ax * inv + b.x + r.x;
    val.y = ay * inv + b.y + r.y;
    val.z = az * inv + b.z + r.z;
    val.w = aw * inv + b.w + r.w;

    float m = (lane < 10) ? fmaxf(fmaxf(val.x, val.y), fmaxf(val.z, val.w)) : -3.4e38f;
#pragma unroll
    for (int o = 16; o; o >>= 1) m = fmaxf(m, __shfl_xor_sync(FULL, m, o));
    float se = (lane < 10)
        ? (__expf(val.x - m) + __expf(val.y - m) + __expf(val.z - m) + __expf(val.w - m))
        : 0.f;
#pragma unroll
    for (int o = 16; o; o >>= 1) se += __shfl_xor_sync(FULL, se, o);
    const float lse = m + logf(se);

    if (lane < 10) {
        float4 o4;
        o4.x = val.x - lse; o4.y = val.y - lse;
        o4.z = val.z - lse; o4.w = val.w - lse;
        ((float4*)(out + (size_t)d * NCLS))[sub] = o4;
    }
}

// ---------------- launch ------------------------------------------------------
extern "C" void kernel_launch(void* const* d_in, const int* in_sizes, int n_in,
                              void* d_out, int out_size)
{
    const float* x   = (const float*)d_in[0];
    const int*   ei  = (const int*)d_in[1];
    const float* W1  = (const float*)d_in[2];
    const float* as1 = (const float*)d_in[3];
    const float* ad1 = (const float*)d_in[4];
    const float* b1  = (const float*)d_in[5];
    const float* W2  = (const float*)d_in[6];
    const float* as2 = (const float*)d_in[7];
    const float* ad2 = (const float*)d_in[8];
    const float* b2  = (const float*)d_in[9];
    const float* r1W = (const float*)d_in[10];
    const float* r1b = (const float*)d_in[11];
    const float* r2W = (const float*)d_in[12];
    const float* r2b = (const float*)d_in[13];

    const int E = in_sizes[1] / 2;

    static cudaStream_t s_csr = nullptr;
    static cudaEvent_t ev_fork = nullptr, ev_join = nullptr;
    if (s_csr == nullptr) {
        cudaStreamCreate(&s_csr);
        cudaEventCreateWithFlags(&ev_fork, cudaEventDisableTiming);
        cudaEventCreateWithFlags(&ev_join, cudaEventDisableTiming);
    }

    // main stream: detect (needed by CSR branch), then fork
    k_detect<<<1, 32>>>(ei);
    cudaEventRecord(ev_fork, 0);
    cudaStreamWaitEvent(s_csr, ev_fork, 0);

    // CSR branch (independent of gemm1)
    k_zero   <<<(NNODES + 255) / 256, 256, 0, s_csr>>>();
    k_hist   <<<(E + 255) / 256, 256, 0, s_csr>>>(ei, E);
    k_scanA  <<<SCAN_BLKS, 1024, 0, s_csr>>>();
    k_scanB  <<<1, 128, 0, s_csr>>>();
    k_scanC  <<<SCAN_BLKS, 1024, 0, s_csr>>>();
    k_scatter<<<(E + 255) / 256, 256, 0, s_csr>>>(ei, E);
    cudaEventRecord(ev_join, s_csr);

    // main stream: gemm1 runs concurrently with CSR build
    k_gemm1  <<<NNODES / 32, 128>>>(x, W1, r1W, r1b, as1, ad1);

    // join: edge1agg needs both gemm1 and the CSR
    cudaStreamWaitEvent(0, ev_join, 0);
    k_edge1agg<<<(NNODES + 7) / 8, 256>>>(b1);
    k_gemm2  <<<(NNODES + 63) / 64, 160>>>(W2, r2W, r2b, as2, ad2);
    k_edge2fin<<<(NNODES + 7) / 8, 256>>>(b2, (float*)d_out);
}